// round 2
// baseline (speedup 1.0000x reference)
#include <cuda_runtime.h>
#include <math.h>

#define B_    4
#define N_    8192
#define D_    64
#define S_    1024
#define K_    32
#define CIN_  134
#define HID_  128
#define COUT_ 256
#define C8_   32
#define P_    131072   // B_*S_*K_
#define CTOT_ 518

// ---------------- scratch (device globals; no allocations allowed) --------
__device__ float g_Y [(size_t)CTOT_ * P_];   // dense concat buffer, channel-major
__device__ float g_Xs[(size_t)COUT_ * P_];   // pre-BN conv output scratch
__device__ float g_XD[(size_t)COUT_ * P_];   // final conv (post BN+relu)
__device__ float g_feat[B_*COUT_*S_];
__device__ float g_q[B_*C8_*S_];
__device__ float g_k[B_*C8_*S_];
__device__ float g_v[B_*COUT_*S_];
__device__ float g_E [(size_t)B_*S_*S_];
__device__ float g_Ec[B_*COUT_*COUT_];
__device__ float g_outp[B_*COUT_*S_];
__device__ float g_outc[B_*COUT_*S_];
__device__ float g_mean[COUT_];
__device__ float g_istd[COUT_];
__device__ int   g_fps [B_*S_];
__device__ float g_nxyz[B_*S_*3];
__device__ int   g_ball[B_*S_*K_];

// ---------------- FPS ------------------------------------------------------
__global__ void fps_kernel(const float* __restrict__ xyz, float* __restrict__ outxyz)
{
    int b = blockIdx.x;
    const float* X = xyz + (size_t)b * N_ * 3;
    int tid = threadIdx.x;                 // 1024 threads
    float px[8], py[8], pz[8], dist[8];
#pragma unroll
    for (int i = 0; i < 8; i++){
        int j = tid + i * 1024;
        px[i] = X[j*3+0]; py[i] = X[j*3+1]; pz[i] = X[j*3+2];
        dist[i] = 1e10f;
    }
    __shared__ float s_bv[32];
    __shared__ int   s_bi[32];
    __shared__ float s_c[3];
    __shared__ int   s_far;
    if (tid == 0){ s_far = 0; s_c[0] = X[0]; s_c[1] = X[1]; s_c[2] = X[2]; }
    __syncthreads();

    for (int t = 0; t < S_; t++){
        int   far = s_far;
        float cx = s_c[0], cy = s_c[1], cz = s_c[2];
        if (tid == 0){
            g_fps[b*S_ + t] = far;
            g_nxyz[(b*S_+t)*3+0] = cx;
            g_nxyz[(b*S_+t)*3+1] = cy;
            g_nxyz[(b*S_+t)*3+2] = cz;
            outxyz[(b*S_+t)*3+0] = cx;
            outxyz[(b*S_+t)*3+1] = cy;
            outxyz[(b*S_+t)*3+2] = cz;
        }
        float bv = -1.0f; int bi = 0;
#pragma unroll
        for (int i = 0; i < 8; i++){
            float dx = px[i]-cx, dy = py[i]-cy, dz = pz[i]-cz;
            float d = fmaf(dz, dz, fmaf(dy, dy, dx*dx));
            float nd = fminf(dist[i], d);
            dist[i] = nd;
            if (nd > bv){ bv = nd; bi = tid + i*1024; }   // ties keep lowest j (ascending)
        }
        for (int off = 16; off; off >>= 1){
            float ov = __shfl_down_sync(0xffffffffu, bv, off);
            int   oi = __shfl_down_sync(0xffffffffu, bi, off);
            if (ov > bv || (ov == bv && oi < bi)){ bv = ov; bi = oi; }
        }
        if ((tid & 31) == 0){ s_bv[tid>>5] = bv; s_bi[tid>>5] = bi; }
        __syncthreads();
        if (tid < 32){
            bv = s_bv[tid]; bi = s_bi[tid];
            for (int off = 16; off; off >>= 1){
                float ov = __shfl_down_sync(0xffffffffu, bv, off);
                int   oi = __shfl_down_sync(0xffffffffu, bi, off);
                if (ov > bv || (ov == bv && oi < bi)){ bv = ov; bi = oi; }
            }
            if (tid == 0){
                s_far = bi;
                s_c[0] = X[bi*3+0]; s_c[1] = X[bi*3+1]; s_c[2] = X[bi*3+2];
            }
        }
        __syncthreads();
    }
}

// ---------------- ball query (one warp per center) -------------------------
// Replicates the reference arithmetic exactly:
//   cn2, pn2 : non-fma rounded mul/add chains (XLA reduce of x*x)
//   dot      : fma chain in k-ascending order (cublas-style K=3 dot)
//   d        : fl( fl(cn2 + pn2) - fl(2*dot) )
//   in-ball  : !(d > 0.04f)   (python 0.2*0.2 weak-cast to f32)
__global__ void ball_kernel(const float* __restrict__ xyz)
{
    int gw   = (blockIdx.x * blockDim.x + threadIdx.x) >> 5;   // 0..B*S-1 (grid exact)
    int lane = threadIdx.x & 31;
    int b = gw >> 10;
    const float* X = xyz + (size_t)b * N_ * 3;
    float cx = g_nxyz[gw*3+0], cy = g_nxyz[gw*3+1], cz = g_nxyz[gw*3+2];
    float cn2 = __fadd_rn(__fadd_rn(__fmul_rn(cx,cx), __fmul_rn(cy,cy)), __fmul_rn(cz,cz));
    int* out = g_ball + gw * K_;
    int cnt = 0;
    for (int base = 0; base < N_ && cnt < K_; base += 32){
        int j = base + lane;
        float x = X[j*3+0], y = X[j*3+1], z = X[j*3+2];
        float pn2 = __fadd_rn(__fadd_rn(__fmul_rn(x,x), __fmul_rn(y,y)), __fmul_rn(z,z));
        float dt  = fmaf(cz, z, fmaf(cy, y, __fmul_rn(cx, x)));
        float d   = __fsub_rn(__fadd_rn(cn2, pn2), __fmul_rn(2.0f, dt));
        bool inb = !(d > 0.04f);
        unsigned msk = __ballot_sync(0xffffffffu, inb);
        int pos = cnt + __popc(msk & ((1u << lane) - 1u));
        if (inb && pos < K_) out[pos] = j;
        cnt += __popc(msk);
    }
    __syncwarp();
    if (cnt < K_){
        int first = out[0];
        for (int p = cnt + lane; p < K_; p += 32) out[p] = first;
    }
}

// ---------------- build x0 into g_Y channels [0,134) ------------------------
__global__ void build_x0(const float* __restrict__ xyz, const float* __restrict__ pts)
{
    int bs  = blockIdx.x;                   // 0..B*S-1
    int b   = bs >> 10;
    int tid = threadIdx.x;                  // 256
    __shared__ int   sj[32];
    __shared__ float sgx[32], sgy[32], sgz[32];
    __shared__ float scp[64];
    __shared__ float scen[3];
    if (tid < 32){
        int j = g_ball[bs*K_ + tid]; sj[tid] = j;
        const float* Xp = xyz + ((size_t)b*N_ + j)*3;
        sgx[tid] = Xp[0]; sgy[tid] = Xp[1]; sgz[tid] = Xp[2];
    } else if (tid < 96){
        scp[tid-32] = pts[((size_t)b*N_ + g_fps[bs])*D_ + (tid-32)];
    } else if (tid < 99){
        scen[tid-96] = g_nxyz[bs*3 + (tid-96)];
    }
    __syncthreads();
    const float* Pb = pts + (size_t)b * N_ * D_;
    size_t pbase = (size_t)bs * K_;
    for (int idx = tid; idx < CIN_ * K_; idx += 256){
        int c = idx >> 5, k = idx & 31;
        int j = sj[k];
        float val;
        if (c < 3){
            float g = (c==0) ? sgx[k] : (c==1) ? sgy[k] : sgz[k];
            float cc = scen[c];
            val = (g - cc) - cc;                     // grouped_norm - new_xyz
        } else if (c < 67){
            val = Pb[(size_t)j*D_ + (c-3)] - scp[c-3];
        } else if (c < 70){
            int c3 = c - 67;
            float g = (c3==0) ? sgx[k] : (c3==1) ? sgy[k] : sgz[k];
            val = g - scen[c3];                      // grouped_norm
        } else {
            val = Pb[(size_t)j*D_ + (c-70)];
        }
        g_Y[(size_t)c*P_ + pbase + k] = val;
    }
}

// ---------------- GEMMs (64x64 tile, 256 threads, 4x4/thread) --------------
// C[m][n] = sum_k A[m*K+k] * B[k*N+n]   (row-major A, K-major B)
__global__ void gemm_nn(const float* __restrict__ A, const float* __restrict__ Bm,
                        float* __restrict__ C, const float* __restrict__ bias,
                        int M, int Nn, int Kk, long sA, long sB, long sC)
{
    A  += (long)blockIdx.z * sA;
    Bm += (long)blockIdx.z * sB;
    C  += (long)blockIdx.z * sC;
    __shared__ float As[16][68];
    __shared__ float Bs[16][64];
    int tid = threadIdx.x;
    int m0 = blockIdx.y * 64, n0 = blockIdx.x * 64;
    int ty = tid >> 4, tx = tid & 15;
    float acc[4][4] = {};
    for (int k0 = 0; k0 < Kk; k0 += 16){
#pragma unroll
        for (int i = tid; i < 1024; i += 256){
            int rr = i >> 4, cc = i & 15;
            int mm = m0 + rr, kk = k0 + cc;
            As[cc][rr] = (mm < M && kk < Kk) ? A[(long)mm*Kk + kk] : 0.f;
        }
#pragma unroll
        for (int i = tid; i < 1024; i += 256){
            int rr = i >> 6, cc = i & 63;
            int kk = k0 + rr;
            Bs[rr][cc] = (kk < Kk) ? Bm[(long)kk*Nn + n0 + cc] : 0.f;
        }
        __syncthreads();
#pragma unroll
        for (int kk = 0; kk < 16; kk++){
            float4 a  = *(const float4*)&As[kk][ty*4];
            float4 bv = *(const float4*)&Bs[kk][tx*4];
            float av[4] = {a.x, a.y, a.z, a.w};
            float bb[4] = {bv.x, bv.y, bv.z, bv.w};
#pragma unroll
            for (int i = 0; i < 4; i++)
#pragma unroll
                for (int j = 0; j < 4; j++)
                    acc[i][j] = fmaf(av[i], bb[j], acc[i][j]);
        }
        __syncthreads();
    }
#pragma unroll
    for (int i = 0; i < 4; i++){
        int mm = m0 + ty*4 + i;
        if (mm < M){
            float bsv = bias ? bias[mm] : 0.f;
            float4 o = make_float4(acc[i][0]+bsv, acc[i][1]+bsv, acc[i][2]+bsv, acc[i][3]+bsv);
            *(float4*)&C[(long)mm*Nn + n0 + tx*4] = o;
        }
    }
}

// C[m][n] = sum_k A[k*lda+m] * B[k*ldb+n]
__global__ void gemm_tn(const float* __restrict__ A, const float* __restrict__ Bm,
                        float* __restrict__ C,
                        int M, int Nn, int Kk, int lda, int ldb,
                        long sA, long sB, long sC)
{
    A += (long)blockIdx.z*sA; Bm += (long)blockIdx.z*sB; C += (long)blockIdx.z*sC;
    __shared__ float As[16][64], Bs[16][64];
    int tid = threadIdx.x;
    int m0 = blockIdx.y * 64, n0 = blockIdx.x * 64;
    int ty = tid >> 4, tx = tid & 15;
    float acc[4][4] = {};
    for (int k0 = 0; k0 < Kk; k0 += 16){
#pragma unroll
        for (int i = tid; i < 1024; i += 256){
            int rr = i >> 6, cc = i & 63;
            int kk = k0 + rr;
            As[rr][cc] = (kk < Kk) ? A[(long)kk*lda + m0 + cc] : 0.f;
            Bs[rr][cc] = (kk < Kk) ? Bm[(long)kk*ldb + n0 + cc] : 0.f;
        }
        __syncthreads();
#pragma unroll
        for (int kk = 0; kk < 16; kk++){
            float4 a  = *(const float4*)&As[kk][ty*4];
            float4 bv = *(const float4*)&Bs[kk][tx*4];
            float av[4] = {a.x, a.y, a.z, a.w};
            float bb[4] = {bv.x, bv.y, bv.z, bv.w};
#pragma unroll
            for (int i = 0; i < 4; i++)
#pragma unroll
                for (int j = 0; j < 4; j++)
                    acc[i][j] = fmaf(av[i], bb[j], acc[i][j]);
        }
        __syncthreads();
    }
#pragma unroll
    for (int i = 0; i < 4; i++){
        int mm = m0 + ty*4 + i;
        float4 o = make_float4(acc[i][0], acc[i][1], acc[i][2], acc[i][3]);
        *(float4*)&C[(long)mm*Nn + n0 + tx*4] = o;
    }
}

// C[m][n] = sum_k A[m*lda+k] * B[n*ldb+k]
__global__ void gemm_nt(const float* __restrict__ A, const float* __restrict__ Bm,
                        float* __restrict__ C,
                        int M, int Nn, int Kk, int lda, int ldb,
                        long sA, long sB, long sC)
{
    A += (long)blockIdx.z*sA; Bm += (long)blockIdx.z*sB; C += (long)blockIdx.z*sC;
    __shared__ float As[16][68], Bs[16][68];
    int tid = threadIdx.x;
    int m0 = blockIdx.y * 64, n0 = blockIdx.x * 64;
    int ty = tid >> 4, tx = tid & 15;
    float acc[4][4] = {};
    for (int k0 = 0; k0 < Kk; k0 += 16){
#pragma unroll
        for (int i = tid; i < 1024; i += 256){
            int mm = i >> 4, kd = i & 15;
            int kk = k0 + kd;
            As[kd][mm] = (kk < Kk) ? A[(long)(m0+mm)*lda + kk] : 0.f;
            Bs[kd][mm] = (kk < Kk) ? Bm[(long)(n0+mm)*ldb + kk] : 0.f;
        }
        __syncthreads();
#pragma unroll
        for (int kk = 0; kk < 16; kk++){
            float4 a  = *(const float4*)&As[kk][ty*4];
            float4 bv = *(const float4*)&Bs[kk][tx*4];
            float av[4] = {a.x, a.y, a.z, a.w};
            float bb[4] = {bv.x, bv.y, bv.z, bv.w};
#pragma unroll
            for (int i = 0; i < 4; i++)
#pragma unroll
                for (int j = 0; j < 4; j++)
                    acc[i][j] = fmaf(av[i], bb[j], acc[i][j]);
        }
        __syncthreads();
    }
#pragma unroll
    for (int i = 0; i < 4; i++){
        int mm = m0 + ty*4 + i;
        float4 o = make_float4(acc[i][0], acc[i][1], acc[i][2], acc[i][3]);
        *(float4*)&C[(long)mm*Nn + n0 + tx*4] = o;
    }
}

// ---- f64-accumulating small GEMMs for the channel-attention path ----------
// C[m][n] = sum_k A[m*lda+k]*B[n*ldb+k]   (NT, double accumulation)
__global__ void gemm_nt_f64(const float* __restrict__ A, const float* __restrict__ Bm,
                            float* __restrict__ C, int M, int Nn, int Kk,
                            int lda, int ldb, long sA, long sB, long sC)
{
    A += (long)blockIdx.z*sA; Bm += (long)blockIdx.z*sB; C += (long)blockIdx.z*sC;
    __shared__ float As[16][17], Bs[16][17];
    int tx = threadIdx.x, ty = threadIdx.y;     // (16,16)
    int m = blockIdx.y*16 + ty, n0 = blockIdx.x*16;
    double acc = 0.0;
    for (int k0 = 0; k0 < Kk; k0 += 16){
        As[ty][tx] = A[(long)m*lda + k0 + tx];
        Bs[ty][tx] = Bm[(long)(n0+ty)*ldb + k0 + tx];
        __syncthreads();
#pragma unroll
        for (int kk = 0; kk < 16; kk++)
            acc += (double)As[ty][kk] * (double)Bs[tx][kk];
        __syncthreads();
    }
    C[(long)m*Nn + n0 + tx] = (float)acc;
}

// C[m][n] = sum_k A[m*Kk+k]*B[k*Nn+n]   (NN, double accumulation)
__global__ void gemm_nn_f64(const float* __restrict__ A, const float* __restrict__ Bm,
                            float* __restrict__ C, int M, int Nn, int Kk,
                            long sA, long sB, long sC)
{
    A += (long)blockIdx.z*sA; Bm += (long)blockIdx.z*sB; C += (long)blockIdx.z*sC;
    __shared__ float As[16][17], Bs[16][17];
    int tx = threadIdx.x, ty = threadIdx.y;
    int m = blockIdx.y*16 + ty, n = blockIdx.x*16 + tx;
    double acc = 0.0;
    for (int k0 = 0; k0 < Kk; k0 += 16){
        As[ty][tx] = A[(long)m*Kk + k0 + tx];
        Bs[ty][tx] = Bm[(long)(k0+ty)*Nn + n];
        __syncthreads();
#pragma unroll
        for (int kk = 0; kk < 16; kk++)
            acc += (double)As[ty][kk] * (double)Bs[kk][tx];
        __syncthreads();
    }
    C[(long)m*Nn + n] = (float)acc;
}

// ---------------- BatchNorm (training mode) ---------------------------------
__global__ void bn_stats(const float* __restrict__ Xs)
{
    int c = blockIdx.x;
    const float* xp = Xs + (size_t)c * P_;
    int tid = threadIdx.x;
    double s = 0.0, ss = 0.0;
    for (int p = tid; p < P_; p += 256){
        float v = xp[p];
        s  += (double)v;
        ss += (double)v * (double)v;
    }
    __shared__ double sh0[256], sh1[256];
    sh0[tid] = s; sh1[tid] = ss; __syncthreads();
    for (int off = 128; off; off >>= 1){
        if (tid < off){ sh0[tid] += sh0[tid+off]; sh1[tid] += sh1[tid+off]; }
        __syncthreads();
    }
    if (tid == 0){
        double m   = sh0[0] / (double)P_;
        double var = sh1[0] / (double)P_ - m*m;
        g_mean[c] = (float)m;
        g_istd[c] = (float)(1.0 / sqrt(var + 1e-5));
    }
}

__global__ void bn_apply_relu(const float* __restrict__ Xs, float* __restrict__ dst,
                              const float* __restrict__ gg, const float* __restrict__ be)
{
    size_t i = (size_t)blockIdx.x * 256 + threadIdx.x;
    int c = (int)(i >> 17);            // P_ = 2^17
    float v = (Xs[i] - g_mean[c]) * g_istd[c] * gg[c] + be[c];
    dst[i] = fmaxf(v, 0.f);
}

// ---------------- max over K -------------------------------------------------
__global__ void maxk_kernel()
{
    int i = blockIdx.x * 256 + threadIdx.x;           // over B*COUT*S = 2^20
    int s = i & 1023, c = (i >> 10) & 255, b = i >> 18;
    const float* src = g_XD + (size_t)c * P_ + ((size_t)(b*S_ + s)) * K_;
    float m = src[0];
#pragma unroll
    for (int k = 1; k < K_; k++) m = fmaxf(m, src[k]);
    g_feat[i] = m;
}

// ---------------- softmaxes ---------------------------------------------------
__global__ void softmax_rows_1024(float* __restrict__ E)
{
    int row = blockIdx.x;
    float* e = E + (size_t)row * 1024;
    int tid = threadIdx.x;
    __shared__ float sh[256];
    float mx = -3.402823466e38f;
    for (int c = tid; c < 1024; c += 256) mx = fmaxf(mx, e[c]);
    sh[tid] = mx; __syncthreads();
    for (int off = 128; off; off >>= 1){ if (tid < off) sh[tid] = fmaxf(sh[tid], sh[tid+off]); __syncthreads(); }
    mx = sh[0]; __syncthreads();
    float sum = 0.f;
    float vals[4];
#pragma unroll
    for (int q = 0; q < 4; q++){
        int c = tid + q*256;
        float v = expf(e[c] - mx);
        vals[q] = v; sum += v;
    }
    sh[tid] = sum; __syncthreads();
    for (int off = 128; off; off >>= 1){ if (tid < off) sh[tid] += sh[tid+off]; __syncthreads(); }
    float inv = 1.0f / sh[0];
#pragma unroll
    for (int q = 0; q < 4; q++) e[tid + q*256] = vals[q] * inv;
}

// channel-attention softmax: t = rowmax(e) - e, softmax(t), all in f64
__global__ void softmax_c_kernel(float* __restrict__ E)
{
    int row = blockIdx.x;                   // B*COUT rows of 256
    float* e = E + (size_t)row * 256;
    int tid = threadIdx.x;
    __shared__ double sh[256];
    double v = (double)e[tid];
    sh[tid] = v; __syncthreads();
    for (int off = 128; off; off >>= 1){ if (tid < off) sh[tid] = fmax(sh[tid], sh[tid+off]); __syncthreads(); }
    double m1 = sh[0]; __syncthreads();
    double t = m1 - v;                      // energy_c transform (literal)
    sh[tid] = t; __syncthreads();
    for (int off = 128; off; off >>= 1){ if (tid < off) sh[tid] = fmax(sh[tid], sh[tid+off]); __syncthreads(); }
    double mt = sh[0]; __syncthreads();
    double ex = exp(t - mt);
    sh[tid] = ex; __syncthreads();
    for (int off = 128; off; off >>= 1){ if (tid < off) sh[tid] += sh[tid+off]; __syncthreads(); }
    e[tid] = (float)(ex / sh[0]);
}

// ---------------- finalize -----------------------------------------------------
__global__ void finalize_kernel(float* __restrict__ out, const float* __restrict__ gamma)
{
    int i = blockIdx.x * 256 + threadIdx.x;   // output-major (b,s,c), 2^20 total
    int c = i & 255, s = (i >> 8) & 1023, b = i >> 18;
    size_t f = ((size_t)(b*COUT_ + c)) * S_ + s;
    float g = gamma[0];
    float val = g * (g_outp[f] + g_outc[f]) + 2.0f * g_feat[f];
    out[(size_t)B_*S_*3 + i] = val;
}

// ---------------- launch -------------------------------------------------------
extern "C" void kernel_launch(void* const* d_in, const int* in_sizes, int n_in,
                              void* d_out, int out_size)
{
    const float* xyz    = (const float*)d_in[0];
    const float* points = (const float*)d_in[1];
    const float* W[4]  = {(const float*)d_in[2],  (const float*)d_in[6],
                          (const float*)d_in[10], (const float*)d_in[14]};
    const float* gl[4] = {(const float*)d_in[4],  (const float*)d_in[8],
                          (const float*)d_in[12], (const float*)d_in[16]};
    const float* bel[4]= {(const float*)d_in[5],  (const float*)d_in[9],
                          (const float*)d_in[13], (const float*)d_in[17]};
    const float* Wq = (const float*)d_in[18]; const float* bq = (const float*)d_in[19];
    const float* Wk = (const float*)d_in[20]; const float* bk = (const float*)d_in[21];
    const float* Wv = (const float*)d_in[22]; const float* bv = (const float*)d_in[23];
    const float* gamma = (const float*)d_in[24];
    float* out = (float*)d_out;

    float *Y, *Xs, *XD, *feat, *q, *k, *v, *E, *Ec, *outp, *outc;
    cudaGetSymbolAddress((void**)&Y,    g_Y);
    cudaGetSymbolAddress((void**)&Xs,   g_Xs);
    cudaGetSymbolAddress((void**)&XD,   g_XD);
    cudaGetSymbolAddress((void**)&feat, g_feat);
    cudaGetSymbolAddress((void**)&q,    g_q);
    cudaGetSymbolAddress((void**)&k,    g_k);
    cudaGetSymbolAddress((void**)&v,    g_v);
    cudaGetSymbolAddress((void**)&E,    g_E);
    cudaGetSymbolAddress((void**)&Ec,   g_Ec);
    cudaGetSymbolAddress((void**)&outp, g_outp);
    cudaGetSymbolAddress((void**)&outc, g_outc);

    // stage 1-2: FPS, ball query, gather/build x0
    fps_kernel<<<B_, 1024>>>(xyz, out);
    ball_kernel<<<(B_*S_*32)/256, 256>>>(xyz);
    build_x0<<<B_*S_, 256>>>(xyz, points);

    // stage 3: DenseNet (conv -> BN stats -> BN+relu into dense buffer)
    int   Kl[4]  = {CIN_, CIN_+HID_, CIN_+2*HID_, CIN_+3*HID_};
    int   COl[4] = {HID_, HID_, HID_, COUT_};
    float* dst[4] = {Y + (size_t)CIN_*P_, Y + (size_t)(CIN_+HID_)*P_,
                     Y + (size_t)(CIN_+2*HID_)*P_, XD};
    for (int l = 0; l < 4; l++){
        gemm_nn<<<dim3(P_/64, COl[l]/64, 1), 256>>>(W[l], Y, Xs, nullptr,
                                                    COl[l], P_, Kl[l], 0, 0, 0);
        bn_stats<<<COl[l], 256>>>(Xs);
        bn_apply_relu<<<(COl[l]*(P_/256)), 256>>>(Xs, dst[l], gl[l], bel[l]);
    }

    // stage 4: max over K
    maxk_kernel<<<(B_*COUT_*S_)/256, 256>>>();

    // stage 5: dual attention
    long fS = (long)COUT_ * S_;
    gemm_nn<<<dim3(S_/64, 1, B_), 256>>>(Wq, feat, q, bq, C8_,  S_, COUT_, 0, fS, (long)C8_*S_);
    gemm_nn<<<dim3(S_/64, 1, B_), 256>>>(Wk, feat, k, bk, C8_,  S_, COUT_, 0, fS, (long)C8_*S_);
    gemm_nn<<<dim3(S_/64, 4, B_), 256>>>(Wv, feat, v, bv, COUT_,S_, COUT_, 0, fS, fS);

    gemm_tn<<<dim3(S_/64, S_/64, B_), 256>>>(q, k, E, S_, S_, C8_, S_, S_,
                                             (long)C8_*S_, (long)C8_*S_, (long)S_*S_);
    softmax_rows_1024<<<B_*S_, 256>>>(E);
    gemm_nt<<<dim3(S_/64, COUT_/64, B_), 256>>>(v, E, outp, COUT_, S_, S_, S_, S_,
                                                fS, (long)S_*S_, fS);

    // channel attention — f64-accumulated energy, f64 softmax, f64-accumulated out_c
    gemm_nt_f64<<<dim3(COUT_/16, COUT_/16, B_), dim3(16,16)>>>(
        feat, feat, Ec, COUT_, COUT_, S_, S_, S_, fS, fS, (long)COUT_*COUT_);
    softmax_c_kernel<<<B_*COUT_, 256>>>(Ec);
    gemm_nn_f64<<<dim3(S_/16, COUT_/16, B_), dim3(16,16)>>>(
        Ec, feat, outc, COUT_, S_, COUT_, (long)COUT_*COUT_, fS, fS);

    finalize_kernel<<<(B_*S_*COUT_)/256, 256>>>(out, gamma);
}

// round 3
// speedup vs baseline: 1.3512x; 1.3512x over previous
#include <cuda_runtime.h>
#include <math.h>

#define B_    4
#define N_    8192
#define D_    64
#define S_    1024
#define K_    32
#define CIN_  134
#define HID_  128
#define COUT_ 256
#define C8_   32
#define P_    131072   // B_*S_*K_
#define CTOT_ 518

// ---------------- scratch (device globals; no allocations allowed) --------
__device__ float g_Y [(size_t)CTOT_ * P_];   // dense concat buffer, channel-major
__device__ float g_Xs[(size_t)COUT_ * P_];   // pre-BN conv output scratch
__device__ float g_XD[(size_t)COUT_ * P_];   // final conv (post BN+relu)
__device__ float g_feat[B_*COUT_*S_];
__device__ float g_q[B_*C8_*S_];
__device__ float g_k[B_*C8_*S_];
__device__ float g_v[B_*COUT_*S_];
__device__ float g_E [(size_t)B_*S_*S_];
__device__ float g_Ec[B_*COUT_*COUT_];
__device__ float g_outp[B_*COUT_*S_];
__device__ float g_outc[B_*COUT_*S_];
__device__ float g_mean[COUT_];
__device__ float g_istd[COUT_];
__device__ double g_part[COUT_*8*2];
__device__ int   g_fps [B_*S_];
__device__ float g_nxyz[B_*S_*3];
__device__ int   g_ball[B_*S_*K_];

// ---------------- FPS ------------------------------------------------------
__global__ void fps_kernel(const float* __restrict__ xyz, float* __restrict__ outxyz)
{
    int b = blockIdx.x;
    const float* X = xyz + (size_t)b * N_ * 3;
    int tid = threadIdx.x;                 // 1024 threads
    float px[8], py[8], pz[8], dist[8];
#pragma unroll
    for (int i = 0; i < 8; i++){
        int j = tid + i * 1024;
        px[i] = X[j*3+0]; py[i] = X[j*3+1]; pz[i] = X[j*3+2];
        dist[i] = 1e10f;
    }
    __shared__ float s_bv[32];
    __shared__ int   s_bi[32];
    __shared__ float s_c[3];
    __shared__ int   s_far;
    if (tid == 0){ s_far = 0; s_c[0] = X[0]; s_c[1] = X[1]; s_c[2] = X[2]; }
    __syncthreads();

    for (int t = 0; t < S_; t++){
        int   far = s_far;
        float cx = s_c[0], cy = s_c[1], cz = s_c[2];
        if (tid == 0){
            g_fps[b*S_ + t] = far;
            g_nxyz[(b*S_+t)*3+0] = cx;
            g_nxyz[(b*S_+t)*3+1] = cy;
            g_nxyz[(b*S_+t)*3+2] = cz;
            outxyz[(b*S_+t)*3+0] = cx;
            outxyz[(b*S_+t)*3+1] = cy;
            outxyz[(b*S_+t)*3+2] = cz;
        }
        float bv = -1.0f; int bi = 0;
#pragma unroll
        for (int i = 0; i < 8; i++){
            float dx = px[i]-cx, dy = py[i]-cy, dz = pz[i]-cz;
            float d = fmaf(dz, dz, fmaf(dy, dy, dx*dx));
            float nd = fminf(dist[i], d);
            dist[i] = nd;
            if (nd > bv){ bv = nd; bi = tid + i*1024; }   // ties keep lowest j (ascending)
        }
        for (int off = 16; off; off >>= 1){
            float ov = __shfl_down_sync(0xffffffffu, bv, off);
            int   oi = __shfl_down_sync(0xffffffffu, bi, off);
            if (ov > bv || (ov == bv && oi < bi)){ bv = ov; bi = oi; }
        }
        if ((tid & 31) == 0){ s_bv[tid>>5] = bv; s_bi[tid>>5] = bi; }
        __syncthreads();
        if (tid < 32){
            bv = s_bv[tid]; bi = s_bi[tid];
            for (int off = 16; off; off >>= 1){
                float ov = __shfl_down_sync(0xffffffffu, bv, off);
                int   oi = __shfl_down_sync(0xffffffffu, bi, off);
                if (ov > bv || (ov == bv && oi < bi)){ bv = ov; bi = oi; }
            }
            if (tid == 0){
                s_far = bi;
                s_c[0] = X[bi*3+0]; s_c[1] = X[bi*3+1]; s_c[2] = X[bi*3+2];
            }
        }
        __syncthreads();
    }
}

// ---------------- ball query (one warp per center) -------------------------
__global__ void ball_kernel(const float* __restrict__ xyz)
{
    int gw   = (blockIdx.x * blockDim.x + threadIdx.x) >> 5;   // 0..B*S-1
    int lane = threadIdx.x & 31;
    int b = gw >> 10;
    const float* X = xyz + (size_t)b * N_ * 3;
    float cx = g_nxyz[gw*3+0], cy = g_nxyz[gw*3+1], cz = g_nxyz[gw*3+2];
    float cn2 = __fadd_rn(__fadd_rn(__fmul_rn(cx,cx), __fmul_rn(cy,cy)), __fmul_rn(cz,cz));
    int* out = g_ball + gw * K_;
    int cnt = 0;
    for (int base = 0; base < N_ && cnt < K_; base += 32){
        int j = base + lane;
        float x = X[j*3+0], y = X[j*3+1], z = X[j*3+2];
        float pn2 = __fadd_rn(__fadd_rn(__fmul_rn(x,x), __fmul_rn(y,y)), __fmul_rn(z,z));
        float dt  = fmaf(cz, z, fmaf(cy, y, __fmul_rn(cx, x)));
        float d   = __fsub_rn(__fadd_rn(cn2, pn2), __fmul_rn(2.0f, dt));
        bool inb = !(d > 0.04f);
        unsigned msk = __ballot_sync(0xffffffffu, inb);
        int pos = cnt + __popc(msk & ((1u << lane) - 1u));
        if (inb && pos < K_) out[pos] = j;
        cnt += __popc(msk);
    }
    __syncwarp();
    if (cnt < K_){
        int first = out[0];
        for (int p = cnt + lane; p < K_; p += 32) out[p] = first;
    }
}

// ---------------- build x0 into g_Y channels [0,134) ------------------------
__global__ void build_x0(const float* __restrict__ xyz, const float* __restrict__ pts)
{
    int bs  = blockIdx.x;                   // 0..B*S-1
    int b   = bs >> 10;
    int tid = threadIdx.x;                  // 256
    __shared__ int   sj[32];
    __shared__ float sgx[32], sgy[32], sgz[32];
    __shared__ float scp[64];
    __shared__ float scen[3];
    if (tid < 32){
        int j = g_ball[bs*K_ + tid]; sj[tid] = j;
        const float* Xp = xyz + ((size_t)b*N_ + j)*3;
        sgx[tid] = Xp[0]; sgy[tid] = Xp[1]; sgz[tid] = Xp[2];
    } else if (tid < 96){
        scp[tid-32] = pts[((size_t)b*N_ + g_fps[bs])*D_ + (tid-32)];
    } else if (tid < 99){
        scen[tid-96] = g_nxyz[bs*3 + (tid-96)];
    }
    __syncthreads();
    const float* Pb = pts + (size_t)b * N_ * D_;
    size_t pbase = (size_t)bs * K_;
    for (int idx = tid; idx < CIN_ * K_; idx += 256){
        int c = idx >> 5, k = idx & 31;
        int j = sj[k];
        float val;
        if (c < 3){
            float g = (c==0) ? sgx[k] : (c==1) ? sgy[k] : sgz[k];
            float cc = scen[c];
            val = (g - cc) - cc;
        } else if (c < 67){
            val = Pb[(size_t)j*D_ + (c-3)] - scp[c-3];
        } else if (c < 70){
            int c3 = c - 67;
            float g = (c3==0) ? sgx[k] : (c3==1) ? sgy[k] : sgz[k];
            val = g - scen[c3];
        } else {
            val = Pb[(size_t)j*D_ + (c-70)];
        }
        g_Y[(size_t)c*P_ + pbase + k] = val;
    }
}

// ---------------- big conv GEMM: 128x128 tile, 256 thr, 8x8/thread ----------
// C[m][n] = sum_k A[m*Kk+k] * B[k*Nn+n] ; Nn, M multiples of 128.
__global__ void __launch_bounds__(256, 2)
gemm128(const float* __restrict__ A, const float* __restrict__ Bm,
        float* __restrict__ C, int M, int Nn, int Kk)
{
    __shared__ float As[8][128];
    __shared__ float Bs[8][128];
    int tid = threadIdx.x;
    int n0 = blockIdx.x * 128, m0 = blockIdx.y * 128;
    int tx = tid & 15, ty = tid >> 4;
    // B-load indices: 8 rows of 128, each thread one float4
    int bk = tid >> 5, bn = (tid & 31) << 2;
    float acc[8][8] = {};
    for (int k0 = 0; k0 < Kk; k0 += 8){
        // load A tile (transposed into As[k][m]); m-fast for conflict-free STS
#pragma unroll
        for (int i = tid; i < 1024; i += 256){
            int kq = i >> 7, mq = i & 127;
            int kg = k0 + kq;
            As[kq][mq] = (kg < Kk) ? A[(long)(m0+mq)*Kk + kg] : 0.f;
        }
        // load B tile: coalesced float4
        {
            int kg = k0 + bk;
            float4 vv = make_float4(0.f,0.f,0.f,0.f);
            if (kg < Kk) vv = *(const float4*)&Bm[(long)kg*Nn + n0 + bn];
            *(float4*)&Bs[bk][bn] = vv;
        }
        __syncthreads();
#pragma unroll
        for (int kk = 0; kk < 8; kk++){
            float4 a0 = *(const float4*)&As[kk][ty*4];
            float4 a1 = *(const float4*)&As[kk][ty*4 + 64];
            float4 b0 = *(const float4*)&Bs[kk][tx*4];
            float4 b1 = *(const float4*)&Bs[kk][tx*4 + 64];
            float av[8] = {a0.x,a0.y,a0.z,a0.w,a1.x,a1.y,a1.z,a1.w};
            float bw[8] = {b0.x,b0.y,b0.z,b0.w,b1.x,b1.y,b1.z,b1.w};
#pragma unroll
            for (int i = 0; i < 8; i++)
#pragma unroll
                for (int j = 0; j < 8; j++)
                    acc[i][j] = fmaf(av[i], bw[j], acc[i][j]);
        }
        __syncthreads();
    }
#pragma unroll
    for (int i = 0; i < 8; i++){
        int mm = m0 + ((i < 4) ? ty*4 + i : 64 + ty*4 + (i-4));
        float* crow = C + (long)mm*Nn + n0;
        *(float4*)&crow[tx*4]      = make_float4(acc[i][0],acc[i][1],acc[i][2],acc[i][3]);
        *(float4*)&crow[tx*4 + 64] = make_float4(acc[i][4],acc[i][5],acc[i][6],acc[i][7]);
    }
}

// ---------------- small GEMMs (64x64 tile) for attention --------------------
__global__ void gemm_nn(const float* __restrict__ A, const float* __restrict__ Bm,
                        float* __restrict__ C, const float* __restrict__ bias,
                        int M, int Nn, int Kk, long sA, long sB, long sC)
{
    A  += (long)blockIdx.z * sA;
    Bm += (long)blockIdx.z * sB;
    C  += (long)blockIdx.z * sC;
    __shared__ float As[16][68];
    __shared__ float Bs[16][64];
    int tid = threadIdx.x;
    int m0 = blockIdx.y * 64, n0 = blockIdx.x * 64;
    int ty = tid >> 4, tx = tid & 15;
    float acc[4][4] = {};
    for (int k0 = 0; k0 < Kk; k0 += 16){
#pragma unroll
        for (int i = tid; i < 1024; i += 256){
            int rr = i >> 4, cc = i & 15;
            int mm = m0 + rr, kk = k0 + cc;
            As[cc][rr] = (mm < M && kk < Kk) ? A[(long)mm*Kk + kk] : 0.f;
        }
#pragma unroll
        for (int i = tid; i < 1024; i += 256){
            int rr = i >> 6, cc = i & 63;
            int kk = k0 + rr;
            Bs[rr][cc] = (kk < Kk) ? Bm[(long)kk*Nn + n0 + cc] : 0.f;
        }
        __syncthreads();
#pragma unroll
        for (int kk = 0; kk < 16; kk++){
            float4 a  = *(const float4*)&As[kk][ty*4];
            float4 bv = *(const float4*)&Bs[kk][tx*4];
            float av[4] = {a.x, a.y, a.z, a.w};
            float bb[4] = {bv.x, bv.y, bv.z, bv.w};
#pragma unroll
            for (int i = 0; i < 4; i++)
#pragma unroll
                for (int j = 0; j < 4; j++)
                    acc[i][j] = fmaf(av[i], bb[j], acc[i][j]);
        }
        __syncthreads();
    }
#pragma unroll
    for (int i = 0; i < 4; i++){
        int mm = m0 + ty*4 + i;
        if (mm < M){
            float bsv = bias ? bias[mm] : 0.f;
            float4 o = make_float4(acc[i][0]+bsv, acc[i][1]+bsv, acc[i][2]+bsv, acc[i][3]+bsv);
            *(float4*)&C[(long)mm*Nn + n0 + tx*4] = o;
        }
    }
}

__global__ void gemm_tn(const float* __restrict__ A, const float* __restrict__ Bm,
                        float* __restrict__ C,
                        int M, int Nn, int Kk, int lda, int ldb,
                        long sA, long sB, long sC)
{
    A += (long)blockIdx.z*sA; Bm += (long)blockIdx.z*sB; C += (long)blockIdx.z*sC;
    __shared__ float As[16][64], Bs[16][64];
    int tid = threadIdx.x;
    int m0 = blockIdx.y * 64, n0 = blockIdx.x * 64;
    int ty = tid >> 4, tx = tid & 15;
    float acc[4][4] = {};
    for (int k0 = 0; k0 < Kk; k0 += 16){
#pragma unroll
        for (int i = tid; i < 1024; i += 256){
            int rr = i >> 6, cc = i & 63;
            int kk = k0 + rr;
            As[rr][cc] = (kk < Kk) ? A[(long)kk*lda + m0 + cc] : 0.f;
            Bs[rr][cc] = (kk < Kk) ? Bm[(long)kk*ldb + n0 + cc] : 0.f;
        }
        __syncthreads();
#pragma unroll
        for (int kk = 0; kk < 16; kk++){
            float4 a  = *(const float4*)&As[kk][ty*4];
            float4 bv = *(const float4*)&Bs[kk][tx*4];
            float av[4] = {a.x, a.y, a.z, a.w};
            float bb[4] = {bv.x, bv.y, bv.z, bv.w};
#pragma unroll
            for (int i = 0; i < 4; i++)
#pragma unroll
                for (int j = 0; j < 4; j++)
                    acc[i][j] = fmaf(av[i], bb[j], acc[i][j]);
        }
        __syncthreads();
    }
#pragma unroll
    for (int i = 0; i < 4; i++){
        int mm = m0 + ty*4 + i;
        float4 o = make_float4(acc[i][0], acc[i][1], acc[i][2], acc[i][3]);
        *(float4*)&C[(long)mm*Nn + n0 + tx*4] = o;
    }
}

__global__ void gemm_nt(const float* __restrict__ A, const float* __restrict__ Bm,
                        float* __restrict__ C,
                        int M, int Nn, int Kk, int lda, int ldb,
                        long sA, long sB, long sC)
{
    A += (long)blockIdx.z*sA; Bm += (long)blockIdx.z*sB; C += (long)blockIdx.z*sC;
    __shared__ float As[16][68], Bs[16][68];
    int tid = threadIdx.x;
    int m0 = blockIdx.y * 64, n0 = blockIdx.x * 64;
    int ty = tid >> 4, tx = tid & 15;
    float acc[4][4] = {};
    for (int k0 = 0; k0 < Kk; k0 += 16){
#pragma unroll
        for (int i = tid; i < 1024; i += 256){
            int mm = i >> 4, kd = i & 15;
            int kk = k0 + kd;
            As[kd][mm] = (kk < Kk) ? A[(long)(m0+mm)*lda + kk] : 0.f;
            Bs[kd][mm] = (kk < Kk) ? Bm[(long)(n0+mm)*ldb + kk] : 0.f;
        }
        __syncthreads();
#pragma unroll
        for (int kk = 0; kk < 16; kk++){
            float4 a  = *(const float4*)&As[kk][ty*4];
            float4 bv = *(const float4*)&Bs[kk][tx*4];
            float av[4] = {a.x, a.y, a.z, a.w};
            float bb[4] = {bv.x, bv.y, bv.z, bv.w};
#pragma unroll
            for (int i = 0; i < 4; i++)
#pragma unroll
                for (int j = 0; j < 4; j++)
                    acc[i][j] = fmaf(av[i], bb[j], acc[i][j]);
        }
        __syncthreads();
    }
#pragma unroll
    for (int i = 0; i < 4; i++){
        int mm = m0 + ty*4 + i;
        float4 o = make_float4(acc[i][0], acc[i][1], acc[i][2], acc[i][3]);
        *(float4*)&C[(long)mm*Nn + n0 + tx*4] = o;
    }
}

// ---- f64-accumulating small GEMMs for the channel-attention path ----------
__global__ void gemm_nt_f64(const float* __restrict__ A, const float* __restrict__ Bm,
                            float* __restrict__ C, int M, int Nn, int Kk,
                            int lda, int ldb, long sA, long sB, long sC)
{
    A += (long)blockIdx.z*sA; Bm += (long)blockIdx.z*sB; C += (long)blockIdx.z*sC;
    __shared__ float As[16][17], Bs[16][17];
    int tx = threadIdx.x, ty = threadIdx.y;     // (16,16)
    int m = blockIdx.y*16 + ty, n0 = blockIdx.x*16;
    double acc = 0.0;
    for (int k0 = 0; k0 < Kk; k0 += 16){
        As[ty][tx] = A[(long)m*lda + k0 + tx];
        Bs[ty][tx] = Bm[(long)(n0+ty)*ldb + k0 + tx];
        __syncthreads();
#pragma unroll
        for (int kk = 0; kk < 16; kk++)
            acc += (double)As[ty][kk] * (double)Bs[tx][kk];
        __syncthreads();
    }
    C[(long)m*Nn + n0 + tx] = (float)acc;
}

__global__ void gemm_nn_f64(const float* __restrict__ A, const float* __restrict__ Bm,
                            float* __restrict__ C, int M, int Nn, int Kk,
                            long sA, long sB, long sC)
{
    A += (long)blockIdx.z*sA; Bm += (long)blockIdx.z*sB; C += (long)blockIdx.z*sC;
    __shared__ float As[16][17], Bs[16][17];
    int tx = threadIdx.x, ty = threadIdx.y;
    int m = blockIdx.y*16 + ty, n = blockIdx.x*16 + tx;
    double acc = 0.0;
    for (int k0 = 0; k0 < Kk; k0 += 16){
        As[ty][tx] = A[(long)m*Kk + k0 + tx];
        Bs[ty][tx] = Bm[(long)(k0+ty)*Nn + n];
        __syncthreads();
#pragma unroll
        for (int kk = 0; kk < 16; kk++)
            acc += (double)As[ty][kk] * (double)Bs[kk][tx];
        __syncthreads();
    }
    C[(long)m*Nn + n] = (float)acc;
}

// ---------------- BatchNorm (training mode) ---------------------------------
// partial stats: grid (C, 8); each block scans P_/8 elements with float4 loads
__global__ void bn_stats_part(const float* __restrict__ Xs)
{
    int c = blockIdx.x, blk = blockIdx.y;
    const float4* xp = (const float4*)(Xs + (size_t)c * P_ + (size_t)blk * (P_/8));
    int tid = threadIdx.x;
    double s = 0.0, ss = 0.0;
    const int nvec = (P_/8)/4;     // 4096 float4
    for (int p = tid; p < nvec; p += 256){
        float4 v = xp[p];
        s  += (double)v.x + (double)v.y + (double)v.z + (double)v.w;
        ss += (double)v.x*v.x + (double)v.y*v.y + (double)v.z*v.z + (double)v.w*v.w;
    }
    __shared__ double sh0[256], sh1[256];
    sh0[tid] = s; sh1[tid] = ss; __syncthreads();
    for (int off = 128; off; off >>= 1){
        if (tid < off){ sh0[tid] += sh0[tid+off]; sh1[tid] += sh1[tid+off]; }
        __syncthreads();
    }
    if (tid == 0){
        g_part[(c*8 + blk)*2 + 0] = sh0[0];
        g_part[(c*8 + blk)*2 + 1] = sh1[0];
    }
}

__global__ void bn_stats_final(int C)
{
    int c = threadIdx.x;
    if (c < C){
        double s = 0.0, ss = 0.0;
#pragma unroll
        for (int j = 0; j < 8; j++){
            s  += g_part[(c*8+j)*2+0];
            ss += g_part[(c*8+j)*2+1];
        }
        double m   = s / (double)P_;
        double var = ss / (double)P_ - m*m;
        g_mean[c] = (float)m;
        g_istd[c] = (float)(1.0 / sqrt(var + 1e-5));
    }
}

__global__ void bn_apply_relu(const float* __restrict__ Xs, float* __restrict__ dst,
                              const float* __restrict__ gg, const float* __restrict__ be)
{
    size_t i = (size_t)blockIdx.x * 256 + threadIdx.x;    // float4 index
    int c = (int)(i >> 15);            // P_/4 = 2^15 float4 per channel
    float m = g_mean[c], is = g_istd[c], gv = gg[c], bb = be[c];
    float4 v = ((const float4*)Xs)[i];
    float4 o;
    o.x = fmaxf((v.x - m)*is*gv + bb, 0.f);
    o.y = fmaxf((v.y - m)*is*gv + bb, 0.f);
    o.z = fmaxf((v.z - m)*is*gv + bb, 0.f);
    o.w = fmaxf((v.w - m)*is*gv + bb, 0.f);
    ((float4*)dst)[i] = o;
}

// ---------------- max over K -------------------------------------------------
__global__ void maxk_kernel()
{
    int i = blockIdx.x * 256 + threadIdx.x;           // over B*COUT*S = 2^20
    int s = i & 1023, c = (i >> 10) & 255, b = i >> 18;
    const float4* src = (const float4*)(g_XD + (size_t)c * P_ + ((size_t)(b*S_ + s)) * K_);
    float4 v0 = src[0];
    float m = fmaxf(fmaxf(v0.x, v0.y), fmaxf(v0.z, v0.w));
#pragma unroll
    for (int k = 1; k < 8; k++){
        float4 v = src[k];
        m = fmaxf(m, fmaxf(fmaxf(v.x, v.y), fmaxf(v.z, v.w)));
    }
    g_feat[i] = m;
}

// ---------------- softmaxes ---------------------------------------------------
__global__ void softmax_rows_1024(float* __restrict__ E)
{
    int row = blockIdx.x;
    float* e = E + (size_t)row * 1024;
    int tid = threadIdx.x;
    __shared__ float sh[256];
    float mx = -3.402823466e38f;
    for (int c = tid; c < 1024; c += 256) mx = fmaxf(mx, e[c]);
    sh[tid] = mx; __syncthreads();
    for (int off = 128; off; off >>= 1){ if (tid < off) sh[tid] = fmaxf(sh[tid], sh[tid+off]); __syncthreads(); }
    mx = sh[0]; __syncthreads();
    float sum = 0.f;
    float vals[4];
#pragma unroll
    for (int q = 0; q < 4; q++){
        int c = tid + q*256;
        float v = expf(e[c] - mx);
        vals[q] = v; sum += v;
    }
    sh[tid] = sum; __syncthreads();
    for (int off = 128; off; off >>= 1){ if (tid < off) sh[tid] += sh[tid+off]; __syncthreads(); }
    float inv = 1.0f / sh[0];
#pragma unroll
    for (int q = 0; q < 4; q++) e[tid + q*256] = vals[q] * inv;
}

// channel-attention softmax: t = rowmax(e) - e, softmax(t), all in f64
__global__ void softmax_c_kernel(float* __restrict__ E)
{
    int row = blockIdx.x;                   // B*COUT rows of 256
    float* e = E + (size_t)row * 256;
    int tid = threadIdx.x;
    __shared__ double sh[256];
    double v = (double)e[tid];
    sh[tid] = v; __syncthreads();
    for (int off = 128; off; off >>= 1){ if (tid < off) sh[tid] = fmax(sh[tid], sh[tid+off]); __syncthreads(); }
    double m1 = sh[0]; __syncthreads();
    double t = m1 - v;
    sh[tid] = t; __syncthreads();
    for (int off = 128; off; off >>= 1){ if (tid < off) sh[tid] = fmax(sh[tid], sh[tid+off]); __syncthreads(); }
    double mt = sh[0]; __syncthreads();
    double ex = exp(t - mt);
    sh[tid] = ex; __syncthreads();
    for (int off = 128; off; off >>= 1){ if (tid < off) sh[tid] += sh[tid+off]; __syncthreads(); }
    e[tid] = (float)(ex / sh[0]);
}

// ---------------- finalize -----------------------------------------------------
__global__ void finalize_kernel(float* __restrict__ out, const float* __restrict__ gamma)
{
    int i = blockIdx.x * 256 + threadIdx.x;   // output-major (b,s,c), 2^20 total
    int c = i & 255, s = (i >> 8) & 1023, b = i >> 18;
    size_t f = ((size_t)(b*COUT_ + c)) * S_ + s;
    float g = gamma[0];
    float val = g * (g_outp[f] + g_outc[f]) + 2.0f * g_feat[f];
    out[(size_t)B_*S_*3 + i] = val;
}

// ---------------- launch -------------------------------------------------------
extern "C" void kernel_launch(void* const* d_in, const int* in_sizes, int n_in,
                              void* d_out, int out_size)
{
    const float* xyz    = (const float*)d_in[0];
    const float* points = (const float*)d_in[1];
    const float* W[4]  = {(const float*)d_in[2],  (const float*)d_in[6],
                          (const float*)d_in[10], (const float*)d_in[14]};
    const float* gl[4] = {(const float*)d_in[4],  (const float*)d_in[8],
                          (const float*)d_in[12], (const float*)d_in[16]};
    const float* bel[4]= {(const float*)d_in[5],  (const float*)d_in[9],
                          (const float*)d_in[13], (const float*)d_in[17]};
    const float* Wq = (const float*)d_in[18]; const float* bq = (const float*)d_in[19];
    const float* Wk = (const float*)d_in[20]; const float* bk = (const float*)d_in[21];
    const float* Wv = (const float*)d_in[22]; const float* bv = (const float*)d_in[23];
    const float* gamma = (const float*)d_in[24];
    float* out = (float*)d_out;

    float *Y, *Xs, *XD, *feat, *q, *k, *v, *E, *Ec, *outp, *outc;
    cudaGetSymbolAddress((void**)&Y,    g_Y);
    cudaGetSymbolAddress((void**)&Xs,   g_Xs);
    cudaGetSymbolAddress((void**)&XD,   g_XD);
    cudaGetSymbolAddress((void**)&feat, g_feat);
    cudaGetSymbolAddress((void**)&q,    g_q);
    cudaGetSymbolAddress((void**)&k,    g_k);
    cudaGetSymbolAddress((void**)&v,    g_v);
    cudaGetSymbolAddress((void**)&E,    g_E);
    cudaGetSymbolAddress((void**)&Ec,   g_Ec);
    cudaGetSymbolAddress((void**)&outp, g_outp);
    cudaGetSymbolAddress((void**)&outc, g_outc);

    // stage 1-2: FPS, ball query, gather/build x0
    fps_kernel<<<B_, 1024>>>(xyz, out);
    ball_kernel<<<(B_*S_*32)/256, 256>>>(xyz);
    build_x0<<<B_*S_, 256>>>(xyz, points);

    // stage 3: DenseNet (conv -> BN stats -> BN+relu into dense buffer)
    int   Kl[4]  = {CIN_, CIN_+HID_, CIN_+2*HID_, CIN_+3*HID_};
    int   COl[4] = {HID_, HID_, HID_, COUT_};
    float* dst[4] = {Y + (size_t)CIN_*P_, Y + (size_t)(CIN_+HID_)*P_,
                     Y + (size_t)(CIN_+2*HID_)*P_, XD};
    for (int l = 0; l < 4; l++){
        gemm128<<<dim3(P_/128, COl[l]/128), 256>>>(W[l], Y, Xs, COl[l], P_, Kl[l]);
        bn_stats_part<<<dim3(COl[l], 8), 256>>>(Xs);
        bn_stats_final<<<1, 256>>>(COl[l]);
        bn_apply_relu<<<(COl[l]*(P_/1024)), 256>>>(Xs, dst[l], gl[l], bel[l]);
    }

    // stage 4: max over K
    maxk_kernel<<<(B_*COUT_*S_)/256, 256>>>();

    // stage 5: dual attention
    long fS = (long)COUT_ * S_;
    gemm_nn<<<dim3(S_/64, 1, B_), 256>>>(Wq, feat, q, bq, C8_,  S_, COUT_, 0, fS, (long)C8_*S_);
    gemm_nn<<<dim3(S_/64, 1, B_), 256>>>(Wk, feat, k, bk, C8_,  S_, COUT_, 0, fS, (long)C8_*S_);
    gemm_nn<<<dim3(S_/64, 4, B_), 256>>>(Wv, feat, v, bv, COUT_,S_, COUT_, 0, fS, fS);

    gemm_tn<<<dim3(S_/64, S_/64, B_), 256>>>(q, k, E, S_, S_, C8_, S_, S_,
                                             (long)C8_*S_, (long)C8_*S_, (long)S_*S_);
    softmax_rows_1024<<<B_*S_, 256>>>(E);
    gemm_nt<<<dim3(S_/64, COUT_/64, B_), 256>>>(v, E, outp, COUT_, S_, S_, S_, S_,
                                                fS, (long)S_*S_, fS);

    // channel attention — f64-accumulated energy, f64 softmax, f64-accumulated out_c
    gemm_nt_f64<<<dim3(COUT_/16, COUT_/16, B_), dim3(16,16)>>>(
        feat, feat, Ec, COUT_, COUT_, S_, S_, S_, fS, fS, (long)COUT_*COUT_);
    softmax_c_kernel<<<B_*COUT_, 256>>>(Ec);
    gemm_nn_f64<<<dim3(S_/16, COUT_/16, B_), dim3(16,16)>>>(
        Ec, feat, outc, COUT_, S_, COUT_, (long)COUT_*COUT_, fS, fS);

    finalize_kernel<<<(B_*S_*COUT_)/256, 256>>>(out, gamma);
}

// round 4
// speedup vs baseline: 1.5237x; 1.1277x over previous
#include <cuda_runtime.h>
#include <math.h>

#define B_    4
#define N_    8192
#define D_    64
#define S_    1024
#define K_    32
#define CIN_  134
#define HID_  128
#define COUT_ 256
#define C8_   32
#define P_    131072   // B_*S_*K_
#define CTOT_ 518

// ---------------- scratch (device globals; no allocations allowed) --------
__device__ float g_Y [(size_t)CTOT_ * P_];   // dense concat buffer, channel-major
__device__ float g_Xs[(size_t)COUT_ * P_];   // pre-BN conv output scratch
__device__ float g_Wt[COUT_ * CTOT_];        // transposed weights (K-major)
__device__ float g_feat[B_*COUT_*S_];
__device__ float g_q[B_*C8_*S_];
__device__ float g_k[B_*C8_*S_];
__device__ float g_v[B_*COUT_*S_];
__device__ float g_E [(size_t)B_*S_*S_];
__device__ float g_Ec[B_*COUT_*COUT_];
__device__ float g_outp[B_*COUT_*S_];
__device__ float g_outc[B_*COUT_*S_];
__device__ float g_mean[COUT_];
__device__ float g_istd[COUT_];
__device__ double g_part[COUT_*8*2];
__device__ int   g_fps [B_*S_];
__device__ float g_nxyz[B_*S_*3];
__device__ int   g_ball[B_*S_*K_];

// ---------------- FPS ------------------------------------------------------
__global__ void fps_kernel(const float* __restrict__ xyz, float* __restrict__ outxyz)
{
    int b = blockIdx.x;
    const float* X = xyz + (size_t)b * N_ * 3;
    int tid = threadIdx.x;                 // 1024 threads
    float px[8], py[8], pz[8], dist[8];
#pragma unroll
    for (int i = 0; i < 8; i++){
        int j = tid + i * 1024;
        px[i] = X[j*3+0]; py[i] = X[j*3+1]; pz[i] = X[j*3+2];
        dist[i] = 1e10f;
    }
    __shared__ float s_bv[32];
    __shared__ int   s_bi[32];
    __shared__ float s_c[3];
    __shared__ int   s_far;
    if (tid == 0){ s_far = 0; s_c[0] = X[0]; s_c[1] = X[1]; s_c[2] = X[2]; }
    __syncthreads();

    for (int t = 0; t < S_; t++){
        int   far = s_far;
        float cx = s_c[0], cy = s_c[1], cz = s_c[2];
        if (tid == 0){
            g_fps[b*S_ + t] = far;
            g_nxyz[(b*S_+t)*3+0] = cx;
            g_nxyz[(b*S_+t)*3+1] = cy;
            g_nxyz[(b*S_+t)*3+2] = cz;
            outxyz[(b*S_+t)*3+0] = cx;
            outxyz[(b*S_+t)*3+1] = cy;
            outxyz[(b*S_+t)*3+2] = cz;
        }
        float bv = -1.0f; int bi = 0;
#pragma unroll
        for (int i = 0; i < 8; i++){
            float dx = px[i]-cx, dy = py[i]-cy, dz = pz[i]-cz;
            float d = fmaf(dz, dz, fmaf(dy, dy, dx*dx));
            float nd = fminf(dist[i], d);
            dist[i] = nd;
            if (nd > bv){ bv = nd; bi = tid + i*1024; }
        }
        for (int off = 16; off; off >>= 1){
            float ov = __shfl_down_sync(0xffffffffu, bv, off);
            int   oi = __shfl_down_sync(0xffffffffu, bi, off);
            if (ov > bv || (ov == bv && oi < bi)){ bv = ov; bi = oi; }
        }
        if ((tid & 31) == 0){ s_bv[tid>>5] = bv; s_bi[tid>>5] = bi; }
        __syncthreads();
        if (tid < 32){
            bv = s_bv[tid]; bi = s_bi[tid];
            for (int off = 16; off; off >>= 1){
                float ov = __shfl_down_sync(0xffffffffu, bv, off);
                int   oi = __shfl_down_sync(0xffffffffu, bi, off);
                if (ov > bv || (ov == bv && oi < bi)){ bv = ov; bi = oi; }
            }
            if (tid == 0){
                s_far = bi;
                s_c[0] = X[bi*3+0]; s_c[1] = X[bi*3+1]; s_c[2] = X[bi*3+2];
            }
        }
        __syncthreads();
    }
}

// ---------------- ball query (one warp per center) -------------------------
__global__ void ball_kernel(const float* __restrict__ xyz)
{
    int gw   = (blockIdx.x * blockDim.x + threadIdx.x) >> 5;
    int lane = threadIdx.x & 31;
    int b = gw >> 10;
    const float* X = xyz + (size_t)b * N_ * 3;
    float cx = g_nxyz[gw*3+0], cy = g_nxyz[gw*3+1], cz = g_nxyz[gw*3+2];
    float cn2 = __fadd_rn(__fadd_rn(__fmul_rn(cx,cx), __fmul_rn(cy,cy)), __fmul_rn(cz,cz));
    int* out = g_ball + gw * K_;
    int cnt = 0;
    for (int base = 0; base < N_ && cnt < K_; base += 32){
        int j = base + lane;
        float x = X[j*3+0], y = X[j*3+1], z = X[j*3+2];
        float pn2 = __fadd_rn(__fadd_rn(__fmul_rn(x,x), __fmul_rn(y,y)), __fmul_rn(z,z));
        float dt  = fmaf(cz, z, fmaf(cy, y, __fmul_rn(cx, x)));
        float d   = __fsub_rn(__fadd_rn(cn2, pn2), __fmul_rn(2.0f, dt));
        bool inb = !(d > 0.04f);
        unsigned msk = __ballot_sync(0xffffffffu, inb);
        int pos = cnt + __popc(msk & ((1u << lane) - 1u));
        if (inb && pos < K_) out[pos] = j;
        cnt += __popc(msk);
    }
    __syncwarp();
    if (cnt < K_){
        int first = out[0];
        for (int p = cnt + lane; p < K_; p += 32) out[p] = first;
    }
}

// ---------------- build x0 into g_Y channels [0,134) ------------------------
__global__ void build_x0(const float* __restrict__ xyz, const float* __restrict__ pts)
{
    int bs  = blockIdx.x;
    int b   = bs >> 10;
    int tid = threadIdx.x;                  // 256
    __shared__ int   sj[32];
    __shared__ float sgx[32], sgy[32], sgz[32];
    __shared__ float scp[64];
    __shared__ float scen[3];
    if (tid < 32){
        int j = g_ball[bs*K_ + tid]; sj[tid] = j;
        const float* Xp = xyz + ((size_t)b*N_ + j)*3;
        sgx[tid] = Xp[0]; sgy[tid] = Xp[1]; sgz[tid] = Xp[2];
    } else if (tid < 96){
        scp[tid-32] = pts[((size_t)b*N_ + g_fps[bs])*D_ + (tid-32)];
    } else if (tid < 99){
        scen[tid-96] = g_nxyz[bs*3 + (tid-96)];
    }
    __syncthreads();
    const float* Pb = pts + (size_t)b * N_ * D_;
    size_t pbase = (size_t)bs * K_;
    for (int idx = tid; idx < CIN_ * K_; idx += 256){
        int c = idx >> 5, k = idx & 31;
        int j = sj[k];
        float val;
        if (c < 3){
            float g = (c==0) ? sgx[k] : (c==1) ? sgy[k] : sgz[k];
            float cc = scen[c];
            val = (g - cc) - cc;
        } else if (c < 67){
            val = Pb[(size_t)j*D_ + (c-3)] - scp[c-3];
        } else if (c < 70){
            int c3 = c - 67;
            float g = (c3==0) ? sgx[k] : (c3==1) ? sgy[k] : sgz[k];
            val = g - scen[c3];
        } else {
            val = Pb[(size_t)j*D_ + (c-70)];
        }
        g_Y[(size_t)c*P_ + pbase + k] = val;
    }
}

// ---------------- weight transpose: W[M][K] -> Wt[K][M] ----------------------
__global__ void transposeW(const float* __restrict__ W, float* __restrict__ Wt,
                           int M, int Kk)
{
    int i = blockIdx.x * 256 + threadIdx.x;
    if (i < M * Kk){
        int m = i / Kk, k = i - m * Kk;
        Wt[(long)k * M + m] = W[i];
    }
}

// ------------- double-buffered conv GEMM: 128x128 tile, 8x8/thread ----------
// C[m][n] = sum_k At[k*M+m] * B[k*Nn+n] ; M, Nn multiples of 128.
__global__ void __launch_bounds__(256, 2)
gemm128db(const float* __restrict__ At, const float* __restrict__ Bm,
          float* __restrict__ C, int M, int Nn, int Kk)
{
    __shared__ float As[2][8][128];
    __shared__ float Bs[2][8][128];
    int tid = threadIdx.x;
    int n0 = blockIdx.x * 128, m0 = blockIdx.y * 128;
    int lr = tid >> 5;              // 0..7 (k within tile)
    int lc = (tid & 31) << 2;       // 0..124
    int tx = tid & 15, ty = tid >> 4;

    const float4 z4 = make_float4(0.f,0.f,0.f,0.f);
    // preload tile 0
    {
        float4 av = (lr < Kk) ? *(const float4*)(At + (long)lr*M  + m0 + lc) : z4;
        float4 bv = (lr < Kk) ? *(const float4*)(Bm + (long)lr*Nn + n0 + lc) : z4;
        *(float4*)&As[0][lr][lc] = av;
        *(float4*)&Bs[0][lr][lc] = bv;
    }
    __syncthreads();

    float acc[8][8] = {};
    int buf = 0;
    for (int k0 = 8; k0 < Kk; k0 += 8){
        int kg = k0 + lr;
        float4 av = (kg < Kk) ? *(const float4*)(At + (long)kg*M  + m0 + lc) : z4;
        float4 bv = (kg < Kk) ? *(const float4*)(Bm + (long)kg*Nn + n0 + lc) : z4;
#pragma unroll
        for (int kk = 0; kk < 8; kk++){
            float4 a0 = *(const float4*)&As[buf][kk][ty*4];
            float4 a1 = *(const float4*)&As[buf][kk][ty*4 + 64];
            float4 b0 = *(const float4*)&Bs[buf][kk][tx*4];
            float4 b1 = *(const float4*)&Bs[buf][kk][tx*4 + 64];
            float a_[8] = {a0.x,a0.y,a0.z,a0.w,a1.x,a1.y,a1.z,a1.w};
            float b_[8] = {b0.x,b0.y,b0.z,b0.w,b1.x,b1.y,b1.z,b1.w};
#pragma unroll
            for (int i = 0; i < 8; i++)
#pragma unroll
                for (int j = 0; j < 8; j++)
                    acc[i][j] = fmaf(a_[i], b_[j], acc[i][j]);
        }
        *(float4*)&As[buf^1][lr][lc] = av;
        *(float4*)&Bs[buf^1][lr][lc] = bv;
        __syncthreads();
        buf ^= 1;
    }
    // last tile
#pragma unroll
    for (int kk = 0; kk < 8; kk++){
        float4 a0 = *(const float4*)&As[buf][kk][ty*4];
        float4 a1 = *(const float4*)&As[buf][kk][ty*4 + 64];
        float4 b0 = *(const float4*)&Bs[buf][kk][tx*4];
        float4 b1 = *(const float4*)&Bs[buf][kk][tx*4 + 64];
        float a_[8] = {a0.x,a0.y,a0.z,a0.w,a1.x,a1.y,a1.z,a1.w};
        float b_[8] = {b0.x,b0.y,b0.z,b0.w,b1.x,b1.y,b1.z,b1.w};
#pragma unroll
        for (int i = 0; i < 8; i++)
#pragma unroll
            for (int j = 0; j < 8; j++)
                acc[i][j] = fmaf(a_[i], b_[j], acc[i][j]);
    }

#pragma unroll
    for (int i = 0; i < 8; i++){
        int mm = m0 + ((i < 4) ? ty*4 + i : 64 + ty*4 + (i-4));
        float* crow = C + (long)mm*Nn + n0;
        *(float4*)&crow[tx*4]      = make_float4(acc[i][0],acc[i][1],acc[i][2],acc[i][3]);
        *(float4*)&crow[tx*4 + 64] = make_float4(acc[i][4],acc[i][5],acc[i][6],acc[i][7]);
    }
}

// ---------------- small GEMMs (64x64 tile) for attention --------------------
__global__ void gemm_nn(const float* __restrict__ A, const float* __restrict__ Bm,
                        float* __restrict__ C, const float* __restrict__ bias,
                        int M, int Nn, int Kk, long sA, long sB, long sC)
{
    A  += (long)blockIdx.z * sA;
    Bm += (long)blockIdx.z * sB;
    C  += (long)blockIdx.z * sC;
    __shared__ float As[16][68];
    __shared__ float Bs[16][64];
    int tid = threadIdx.x;
    int m0 = blockIdx.y * 64, n0 = blockIdx.x * 64;
    int ty = tid >> 4, tx = tid & 15;
    float acc[4][4] = {};
    for (int k0 = 0; k0 < Kk; k0 += 16){
#pragma unroll
        for (int i = tid; i < 1024; i += 256){
            int rr = i >> 4, cc = i & 15;
            int mm = m0 + rr, kk = k0 + cc;
            As[cc][rr] = (mm < M && kk < Kk) ? A[(long)mm*Kk + kk] : 0.f;
        }
#pragma unroll
        for (int i = tid; i < 1024; i += 256){
            int rr = i >> 6, cc = i & 63;
            int kk = k0 + rr;
            Bs[rr][cc] = (kk < Kk) ? Bm[(long)kk*Nn + n0 + cc] : 0.f;
        }
        __syncthreads();
#pragma unroll
        for (int kk = 0; kk < 16; kk++){
            float4 a  = *(const float4*)&As[kk][ty*4];
            float4 bv = *(const float4*)&Bs[kk][tx*4];
            float av[4] = {a.x, a.y, a.z, a.w};
            float bb[4] = {bv.x, bv.y, bv.z, bv.w};
#pragma unroll
            for (int i = 0; i < 4; i++)
#pragma unroll
                for (int j = 0; j < 4; j++)
                    acc[i][j] = fmaf(av[i], bb[j], acc[i][j]);
        }
        __syncthreads();
    }
#pragma unroll
    for (int i = 0; i < 4; i++){
        int mm = m0 + ty*4 + i;
        if (mm < M){
            float bsv = bias ? bias[mm] : 0.f;
            float4 o = make_float4(acc[i][0]+bsv, acc[i][1]+bsv, acc[i][2]+bsv, acc[i][3]+bsv);
            *(float4*)&C[(long)mm*Nn + n0 + tx*4] = o;
        }
    }
}

__global__ void gemm_tn(const float* __restrict__ A, const float* __restrict__ Bm,
                        float* __restrict__ C,
                        int M, int Nn, int Kk, int lda, int ldb,
                        long sA, long sB, long sC)
{
    A += (long)blockIdx.z*sA; Bm += (long)blockIdx.z*sB; C += (long)blockIdx.z*sC;
    __shared__ float As[16][64], Bs[16][64];
    int tid = threadIdx.x;
    int m0 = blockIdx.y * 64, n0 = blockIdx.x * 64;
    int ty = tid >> 4, tx = tid & 15;
    float acc[4][4] = {};
    for (int k0 = 0; k0 < Kk; k0 += 16){
#pragma unroll
        for (int i = tid; i < 1024; i += 256){
            int rr = i >> 6, cc = i & 63;
            int kk = k0 + rr;
            As[rr][cc] = (kk < Kk) ? A[(long)kk*lda + m0 + cc] : 0.f;
            Bs[rr][cc] = (kk < Kk) ? Bm[(long)kk*ldb + n0 + cc] : 0.f;
        }
        __syncthreads();
#pragma unroll
        for (int kk = 0; kk < 16; kk++){
            float4 a  = *(const float4*)&As[kk][ty*4];
            float4 bv = *(const float4*)&Bs[kk][tx*4];
            float av[4] = {a.x, a.y, a.z, a.w};
            float bb[4] = {bv.x, bv.y, bv.z, bv.w};
#pragma unroll
            for (int i = 0; i < 4; i++)
#pragma unroll
                for (int j = 0; j < 4; j++)
                    acc[i][j] = fmaf(av[i], bb[j], acc[i][j]);
        }
        __syncthreads();
    }
#pragma unroll
    for (int i = 0; i < 4; i++){
        int mm = m0 + ty*4 + i;
        float4 o = make_float4(acc[i][0], acc[i][1], acc[i][2], acc[i][3]);
        *(float4*)&C[(long)mm*Nn + n0 + tx*4] = o;
    }
}

__global__ void gemm_nt(const float* __restrict__ A, const float* __restrict__ Bm,
                        float* __restrict__ C,
                        int M, int Nn, int Kk, int lda, int ldb,
                        long sA, long sB, long sC)
{
    A += (long)blockIdx.z*sA; Bm += (long)blockIdx.z*sB; C += (long)blockIdx.z*sC;
    __shared__ float As[16][68], Bs[16][68];
    int tid = threadIdx.x;
    int m0 = blockIdx.y * 64, n0 = blockIdx.x * 64;
    int ty = tid >> 4, tx = tid & 15;
    float acc[4][4] = {};
    for (int k0 = 0; k0 < Kk; k0 += 16){
#pragma unroll
        for (int i = tid; i < 1024; i += 256){
            int mm = i >> 4, kd = i & 15;
            int kk = k0 + kd;
            As[kd][mm] = (kk < Kk) ? A[(long)(m0+mm)*lda + kk] : 0.f;
            Bs[kd][mm] = (kk < Kk) ? Bm[(long)(n0+mm)*ldb + kk] : 0.f;
        }
        __syncthreads();
#pragma unroll
        for (int kk = 0; kk < 16; kk++){
            float4 a  = *(const float4*)&As[kk][ty*4];
            float4 bv = *(const float4*)&Bs[kk][tx*4];
            float av[4] = {a.x, a.y, a.z, a.w};
            float bb[4] = {bv.x, bv.y, bv.z, bv.w};
#pragma unroll
            for (int i = 0; i < 4; i++)
#pragma unroll
                for (int j = 0; j < 4; j++)
                    acc[i][j] = fmaf(av[i], bb[j], acc[i][j]);
        }
        __syncthreads();
    }
#pragma unroll
    for (int i = 0; i < 4; i++){
        int mm = m0 + ty*4 + i;
        float4 o = make_float4(acc[i][0], acc[i][1], acc[i][2], acc[i][3]);
        *(float4*)&C[(long)mm*Nn + n0 + tx*4] = o;
    }
}

// ---- f64-accumulating small GEMMs for the channel-attention path ----------
__global__ void gemm_nt_f64(const float* __restrict__ A, const float* __restrict__ Bm,
                            float* __restrict__ C, int M, int Nn, int Kk,
                            int lda, int ldb, long sA, long sB, long sC)
{
    A += (long)blockIdx.z*sA; Bm += (long)blockIdx.z*sB; C += (long)blockIdx.z*sC;
    __shared__ float As[16][17], Bs[16][17];
    int tx = threadIdx.x, ty = threadIdx.y;
    int m = blockIdx.y*16 + ty, n0 = blockIdx.x*16;
    double acc = 0.0;
    for (int k0 = 0; k0 < Kk; k0 += 16){
        As[ty][tx] = A[(long)m*lda + k0 + tx];
        Bs[ty][tx] = Bm[(long)(n0+ty)*ldb + k0 + tx];
        __syncthreads();
#pragma unroll
        for (int kk = 0; kk < 16; kk++)
            acc += (double)As[ty][kk] * (double)Bs[tx][kk];
        __syncthreads();
    }
    C[(long)m*Nn + n0 + tx] = (float)acc;
}

__global__ void gemm_nn_f64(const float* __restrict__ A, const float* __restrict__ Bm,
                            float* __restrict__ C, int M, int Nn, int Kk,
                            long sA, long sB, long sC)
{
    A += (long)blockIdx.z*sA; Bm += (long)blockIdx.z*sB; C += (long)blockIdx.z*sC;
    __shared__ float As[16][17], Bs[16][17];
    int tx = threadIdx.x, ty = threadIdx.y;
    int m = blockIdx.y*16 + ty, n = blockIdx.x*16 + tx;
    double acc = 0.0;
    for (int k0 = 0; k0 < Kk; k0 += 16){
        As[ty][tx] = A[(long)m*Kk + k0 + tx];
        Bs[ty][tx] = Bm[(long)(k0+ty)*Nn + n];
        __syncthreads();
#pragma unroll
        for (int kk = 0; kk < 16; kk++)
            acc += (double)As[ty][kk] * (double)Bs[kk][tx];
        __syncthreads();
    }
    C[(long)m*Nn + n] = (float)acc;
}

// ---------------- BatchNorm (training mode) ---------------------------------
__global__ void bn_stats_part(const float* __restrict__ Xs)
{
    int c = blockIdx.x, blk = blockIdx.y;
    const float4* xp = (const float4*)(Xs + (size_t)c * P_ + (size_t)blk * (P_/8));
    int tid = threadIdx.x;
    double s = 0.0, ss = 0.0;
    const int nvec = (P_/8)/4;
    for (int p = tid; p < nvec; p += 256){
        float4 v = xp[p];
        s  += (double)v.x + (double)v.y + (double)v.z + (double)v.w;
        ss += (double)v.x*v.x + (double)v.y*v.y + (double)v.z*v.z + (double)v.w*v.w;
    }
    __shared__ double sh0[256], sh1[256];
    sh0[tid] = s; sh1[tid] = ss; __syncthreads();
    for (int off = 128; off; off >>= 1){
        if (tid < off){ sh0[tid] += sh0[tid+off]; sh1[tid] += sh1[tid+off]; }
        __syncthreads();
    }
    if (tid == 0){
        g_part[(c*8 + blk)*2 + 0] = sh0[0];
        g_part[(c*8 + blk)*2 + 1] = sh1[0];
    }
}

__global__ void bn_stats_final(int C)
{
    int c = threadIdx.x;
    if (c < C){
        double s = 0.0, ss = 0.0;
#pragma unroll
        for (int j = 0; j < 8; j++){
            s  += g_part[(c*8+j)*2+0];
            ss += g_part[(c*8+j)*2+1];
        }
        double m   = s / (double)P_;
        double var = ss / (double)P_ - m*m;
        g_mean[c] = (float)m;
        g_istd[c] = (float)(1.0 / sqrt(var + 1e-5));
    }
}

__global__ void bn_apply_relu(const float* __restrict__ Xs, float* __restrict__ dst,
                              const float* __restrict__ gg, const float* __restrict__ be)
{
    size_t i = (size_t)blockIdx.x * 256 + threadIdx.x;    // float4 index
    int c = (int)(i >> 15);            // P_/4 = 2^15 float4 per channel
    float m = g_mean[c], is = g_istd[c], gv = gg[c], bb = be[c];
    float4 v = ((const float4*)Xs)[i];
    float4 o;
    o.x = fmaxf((v.x - m)*is*gv + bb, 0.f);
    o.y = fmaxf((v.y - m)*is*gv + bb, 0.f);
    o.z = fmaxf((v.z - m)*is*gv + bb, 0.f);
    o.w = fmaxf((v.w - m)*is*gv + bb, 0.f);
    ((float4*)dst)[i] = o;
}

// ------- fused layer-4 BN + ReLU + max over K --------------------------------
__global__ void bn_relu_maxk(const float* __restrict__ Xs,
                             const float* __restrict__ gg, const float* __restrict__ be)
{
    int i = blockIdx.x * 256 + threadIdx.x;           // over B*COUT*S = 2^20
    int s = i & 1023, c = (i >> 10) & 255, b = i >> 18;
    float m = g_mean[c], is = g_istd[c], gv = gg[c], bb = be[c];
    float sc = is * gv;
    const float4* src = (const float4*)(Xs + (size_t)c * P_ + ((size_t)(b*S_ + s)) * K_);
    float best = 0.f;   // relu floor — outputs are >= 0
#pragma unroll
    for (int k = 0; k < 8; k++){
        float4 v = src[k];
        best = fmaxf(best, (v.x - m)*sc + bb);
        best = fmaxf(best, (v.y - m)*sc + bb);
        best = fmaxf(best, (v.z - m)*sc + bb);
        best = fmaxf(best, (v.w - m)*sc + bb);
    }
    g_feat[i] = best;
}

// ---------------- softmaxes ---------------------------------------------------
__global__ void softmax_rows_1024(float* __restrict__ E)
{
    int row = blockIdx.x;
    float* e = E + (size_t)row * 1024;
    int tid = threadIdx.x;
    __shared__ float sh[256];
    float mx = -3.402823466e38f;
    for (int c = tid; c < 1024; c += 256) mx = fmaxf(mx, e[c]);
    sh[tid] = mx; __syncthreads();
    for (int off = 128; off; off >>= 1){ if (tid < off) sh[tid] = fmaxf(sh[tid], sh[tid+off]); __syncthreads(); }
    mx = sh[0]; __syncthreads();
    float sum = 0.f;
    float vals[4];
#pragma unroll
    for (int q = 0; q < 4; q++){
        int c = tid + q*256;
        float v = expf(e[c] - mx);
        vals[q] = v; sum += v;
    }
    sh[tid] = sum; __syncthreads();
    for (int off = 128; off; off >>= 1){ if (tid < off) sh[tid] += sh[tid+off]; __syncthreads(); }
    float inv = 1.0f / sh[0];
#pragma unroll
    for (int q = 0; q < 4; q++) e[tid + q*256] = vals[q] * inv;
}

__global__ void softmax_c_kernel(float* __restrict__ E)
{
    int row = blockIdx.x;                   // B*COUT rows of 256
    float* e = E + (size_t)row * 256;
    int tid = threadIdx.x;
    __shared__ double sh[256];
    double v = (double)e[tid];
    sh[tid] = v; __syncthreads();
    for (int off = 128; off; off >>= 1){ if (tid < off) sh[tid] = fmax(sh[tid], sh[tid+off]); __syncthreads(); }
    double m1 = sh[0]; __syncthreads();
    double t = m1 - v;
    sh[tid] = t; __syncthreads();
    for (int off = 128; off; off >>= 1){ if (tid < off) sh[tid] = fmax(sh[tid], sh[tid+off]); __syncthreads(); }
    double mt = sh[0]; __syncthreads();
    double ex = exp(t - mt);
    sh[tid] = ex; __syncthreads();
    for (int off = 128; off; off >>= 1){ if (tid < off) sh[tid] += sh[tid+off]; __syncthreads(); }
    e[tid] = (float)(ex / sh[0]);
}

// ---------------- finalize -----------------------------------------------------
__global__ void finalize_kernel(float* __restrict__ out, const float* __restrict__ gamma)
{
    int i = blockIdx.x * 256 + threadIdx.x;   // output-major (b,s,c), 2^20 total
    int c = i & 255, s = (i >> 8) & 1023, b = i >> 18;
    size_t f = ((size_t)(b*COUT_ + c)) * S_ + s;
    float g = gamma[0];
    float val = g * (g_outp[f] + g_outc[f]) + 2.0f * g_feat[f];
    out[(size_t)B_*S_*3 + i] = val;
}

// ---------------- launch -------------------------------------------------------
extern "C" void kernel_launch(void* const* d_in, const int* in_sizes, int n_in,
                              void* d_out, int out_size)
{
    const float* xyz    = (const float*)d_in[0];
    const float* points = (const float*)d_in[1];
    const float* W[4]  = {(const float*)d_in[2],  (const float*)d_in[6],
                          (const float*)d_in[10], (const float*)d_in[14]};
    const float* gl[4] = {(const float*)d_in[4],  (const float*)d_in[8],
                          (const float*)d_in[12], (const float*)d_in[16]};
    const float* bel[4]= {(const float*)d_in[5],  (const float*)d_in[9],
                          (const float*)d_in[13], (const float*)d_in[17]};
    const float* Wq = (const float*)d_in[18]; const float* bq = (const float*)d_in[19];
    const float* Wk = (const float*)d_in[20]; const float* bk = (const float*)d_in[21];
    const float* Wv = (const float*)d_in[22]; const float* bv = (const float*)d_in[23];
    const float* gamma = (const float*)d_in[24];
    float* out = (float*)d_out;

    float *Y, *Xs, *Wt, *feat, *q, *k, *v, *E, *Ec, *outp, *outc;
    cudaGetSymbolAddress((void**)&Y,    g_Y);
    cudaGetSymbolAddress((void**)&Xs,   g_Xs);
    cudaGetSymbolAddress((void**)&Wt,   g_Wt);
    cudaGetSymbolAddress((void**)&feat, g_feat);
    cudaGetSymbolAddress((void**)&q,    g_q);
    cudaGetSymbolAddress((void**)&k,    g_k);
    cudaGetSymbolAddress((void**)&v,    g_v);
    cudaGetSymbolAddress((void**)&E,    g_E);
    cudaGetSymbolAddress((void**)&Ec,   g_Ec);
    cudaGetSymbolAddress((void**)&outp, g_outp);
    cudaGetSymbolAddress((void**)&outc, g_outc);

    // stage 1-2: FPS, ball query, gather/build x0
    fps_kernel<<<B_, 1024>>>(xyz, out);
    ball_kernel<<<(B_*S_*32)/256, 256>>>(xyz);
    build_x0<<<B_*S_, 256>>>(xyz, points);

    // stage 3: DenseNet (transpose W -> conv -> BN stats -> BN+relu)
    int   Kl[4]  = {CIN_, CIN_+HID_, CIN_+2*HID_, CIN_+3*HID_};
    int   COl[4] = {HID_, HID_, HID_, COUT_};
    float* dst[4] = {Y + (size_t)CIN_*P_, Y + (size_t)(CIN_+HID_)*P_,
                     Y + (size_t)(CIN_+2*HID_)*P_, nullptr};
    for (int l = 0; l < 4; l++){
        int Melem = COl[l]*Kl[l];
        transposeW<<<(Melem + 255)/256, 256>>>(W[l], Wt, COl[l], Kl[l]);
        gemm128db<<<dim3(P_/128, COl[l]/128), 256>>>(Wt, Y, Xs, COl[l], P_, Kl[l]);
        bn_stats_part<<<dim3(COl[l], 8), 256>>>(Xs);
        bn_stats_final<<<1, 256>>>(COl[l]);
        if (l < 3)
            bn_apply_relu<<<(COl[l]*(P_/1024)), 256>>>(Xs, dst[l], gl[l], bel[l]);
        else
            bn_relu_maxk<<<(B_*COUT_*S_)/256, 256>>>(Xs, gl[l], bel[l]);   // fused L4 + maxpool
    }

    // stage 5: dual attention
    long fS = (long)COUT_ * S_;
    gemm_nn<<<dim3(S_/64, 1, B_), 256>>>(Wq, feat, q, bq, C8_,  S_, COUT_, 0, fS, (long)C8_*S_);
    gemm_nn<<<dim3(S_/64, 1, B_), 256>>>(Wk, feat, k, bk, C8_,  S_, COUT_, 0, fS, (long)C8_*S_);
    gemm_nn<<<dim3(S_/64, 4, B_), 256>>>(Wv, feat, v, bv, COUT_,S_, COUT_, 0, fS, fS);

    gemm_tn<<<dim3(S_/64, S_/64, B_), 256>>>(q, k, E, S_, S_, C8_, S_, S_,
                                             (long)C8_*S_, (long)C8_*S_, (long)S_*S_);
    softmax_rows_1024<<<B_*S_, 256>>>(E);
    gemm_nt<<<dim3(S_/64, COUT_/64, B_), 256>>>(v, E, outp, COUT_, S_, S_, S_, S_,
                                                fS, (long)S_*S_, fS);

    // channel attention — f64-accumulated energy, f64 softmax, f64-accumulated out_c
    gemm_nt_f64<<<dim3(COUT_/16, COUT_/16, B_), dim3(16,16)>>>(
        feat, feat, Ec, COUT_, COUT_, S_, S_, S_, fS, fS, (long)COUT_*COUT_);
    softmax_c_kernel<<<B_*COUT_, 256>>>(Ec);
    gemm_nn_f64<<<dim3(S_/16, COUT_/16, B_), dim3(16,16)>>>(
        Ec, feat, outc, COUT_, S_, COUT_, (long)COUT_*COUT_, fS, fS);

    finalize_kernel<<<(B_*S_*COUT_)/256, 256>>>(out, gamma);
}

// round 5
// speedup vs baseline: 2.6972x; 1.7701x over previous
#include <cuda_runtime.h>
#include <math.h>

#define B_    4
#define N_    8192
#define D_    64
#define S_    1024
#define K_    32
#define CIN_  134
#define HID_  128
#define COUT_ 256
#define C8_   32
#define P_    131072   // B_*S_*K_
#define CTOT_ 518

// ---------------- scratch (device globals; no allocations allowed) --------
__device__ float g_Y [(size_t)CTOT_ * P_];   // dense concat buffer, channel-major
__device__ float g_Xs[(size_t)COUT_ * P_];   // pre-BN conv output scratch
__device__ float g_Wt[COUT_ * CTOT_];        // transposed weights (K-major)
__device__ float g_feat[B_*COUT_*S_];
__device__ float g_q[B_*C8_*S_];
__device__ float g_k[B_*C8_*S_];
__device__ float g_v[B_*COUT_*S_];
__device__ float g_E [(size_t)B_*S_*S_];
__device__ float g_Ec[B_*COUT_*COUT_];
__device__ float g_outp[B_*COUT_*S_];
__device__ float g_outc[B_*COUT_*S_];
__device__ float g_mean[COUT_];
__device__ float g_istd[COUT_];
__device__ double g_part[COUT_*8*2];
__device__ int   g_fps [B_*S_];
__device__ float g_nxyz[B_*S_*3];
__device__ int   g_ball[B_*S_*K_];

// ---------------- FPS ------------------------------------------------------
__global__ void fps_kernel(const float* __restrict__ xyz, float* __restrict__ outxyz)
{
    int b = blockIdx.x;
    const float* X = xyz + (size_t)b * N_ * 3;
    int tid = threadIdx.x;                 // 1024 threads
    float px[8], py[8], pz[8], dist[8];
#pragma unroll
    for (int i = 0; i < 8; i++){
        int j = tid + i * 1024;
        px[i] = X[j*3+0]; py[i] = X[j*3+1]; pz[i] = X[j*3+2];
        dist[i] = 1e10f;
    }
    __shared__ float s_bv[32];
    __shared__ int   s_bi[32];
    __shared__ float s_c[3];
    __shared__ int   s_far;
    if (tid == 0){ s_far = 0; s_c[0] = X[0]; s_c[1] = X[1]; s_c[2] = X[2]; }
    __syncthreads();

    for (int t = 0; t < S_; t++){
        int   far = s_far;
        float cx = s_c[0], cy = s_c[1], cz = s_c[2];
        if (tid == 0){
            g_fps[b*S_ + t] = far;
            g_nxyz[(b*S_+t)*3+0] = cx;
            g_nxyz[(b*S_+t)*3+1] = cy;
            g_nxyz[(b*S_+t)*3+2] = cz;
            outxyz[(b*S_+t)*3+0] = cx;
            outxyz[(b*S_+t)*3+1] = cy;
            outxyz[(b*S_+t)*3+2] = cz;
        }
        float bv = -1.0f; int bi = 0;
#pragma unroll
        for (int i = 0; i < 8; i++){
            float dx = px[i]-cx, dy = py[i]-cy, dz = pz[i]-cz;
            float d = fmaf(dz, dz, fmaf(dy, dy, dx*dx));
            float nd = fminf(dist[i], d);
            dist[i] = nd;
            if (nd > bv){ bv = nd; bi = tid + i*1024; }
        }
        for (int off = 16; off; off >>= 1){
            float ov = __shfl_down_sync(0xffffffffu, bv, off);
            int   oi = __shfl_down_sync(0xffffffffu, bi, off);
            if (ov > bv || (ov == bv && oi < bi)){ bv = ov; bi = oi; }
        }
        if ((tid & 31) == 0){ s_bv[tid>>5] = bv; s_bi[tid>>5] = bi; }
        __syncthreads();
        if (tid < 32){
            bv = s_bv[tid]; bi = s_bi[tid];
            for (int off = 16; off; off >>= 1){
                float ov = __shfl_down_sync(0xffffffffu, bv, off);
                int   oi = __shfl_down_sync(0xffffffffu, bi, off);
                if (ov > bv || (ov == bv && oi < bi)){ bv = ov; bi = oi; }
            }
            if (tid == 0){
                s_far = bi;
                s_c[0] = X[bi*3+0]; s_c[1] = X[bi*3+1]; s_c[2] = X[bi*3+2];
            }
        }
        __syncthreads();
    }
}

// ---------------- ball query (one warp per center) -------------------------
__global__ void ball_kernel(const float* __restrict__ xyz)
{
    int gw   = (blockIdx.x * blockDim.x + threadIdx.x) >> 5;
    int lane = threadIdx.x & 31;
    int b = gw >> 10;
    const float* X = xyz + (size_t)b * N_ * 3;
    float cx = g_nxyz[gw*3+0], cy = g_nxyz[gw*3+1], cz = g_nxyz[gw*3+2];
    float cn2 = __fadd_rn(__fadd_rn(__fmul_rn(cx,cx), __fmul_rn(cy,cy)), __fmul_rn(cz,cz));
    int* out = g_ball + gw * K_;
    int cnt = 0;
    for (int base = 0; base < N_ && cnt < K_; base += 32){
        int j = base + lane;
        float x = X[j*3+0], y = X[j*3+1], z = X[j*3+2];
        float pn2 = __fadd_rn(__fadd_rn(__fmul_rn(x,x), __fmul_rn(y,y)), __fmul_rn(z,z));
        float dt  = fmaf(cz, z, fmaf(cy, y, __fmul_rn(cx, x)));
        float d   = __fsub_rn(__fadd_rn(cn2, pn2), __fmul_rn(2.0f, dt));
        bool inb = !(d > 0.04f);
        unsigned msk = __ballot_sync(0xffffffffu, inb);
        int pos = cnt + __popc(msk & ((1u << lane) - 1u));
        if (inb && pos < K_) out[pos] = j;
        cnt += __popc(msk);
    }
    __syncwarp();
    if (cnt < K_){
        int first = out[0];
        for (int p = cnt + lane; p < K_; p += 32) out[p] = first;
    }
}

// ---------------- build x0 into g_Y channels [0,134) ------------------------
__global__ void build_x0(const float* __restrict__ xyz, const float* __restrict__ pts)
{
    int bs  = blockIdx.x;
    int b   = bs >> 10;
    int tid = threadIdx.x;                  // 256
    __shared__ int   sj[32];
    __shared__ float sgx[32], sgy[32], sgz[32];
    __shared__ float scp[64];
    __shared__ float scen[3];
    if (tid < 32){
        int j = g_ball[bs*K_ + tid]; sj[tid] = j;
        const float* Xp = xyz + ((size_t)b*N_ + j)*3;
        sgx[tid] = Xp[0]; sgy[tid] = Xp[1]; sgz[tid] = Xp[2];
    } else if (tid < 96){
        scp[tid-32] = pts[((size_t)b*N_ + g_fps[bs])*D_ + (tid-32)];
    } else if (tid < 99){
        scen[tid-96] = g_nxyz[bs*3 + (tid-96)];
    }
    __syncthreads();
    const float* Pb = pts + (size_t)b * N_ * D_;
    size_t pbase = (size_t)bs * K_;
    for (int idx = tid; idx < CIN_ * K_; idx += 256){
        int c = idx >> 5, k = idx & 31;
        int j = sj[k];
        float val;
        if (c < 3){
            float g = (c==0) ? sgx[k] : (c==1) ? sgy[k] : sgz[k];
            float cc = scen[c];
            val = (g - cc) - cc;
        } else if (c < 67){
            val = Pb[(size_t)j*D_ + (c-3)] - scp[c-3];
        } else if (c < 70){
            int c3 = c - 67;
            float g = (c3==0) ? sgx[k] : (c3==1) ? sgy[k] : sgz[k];
            val = g - scen[c3];
        } else {
            val = Pb[(size_t)j*D_ + (c-70)];
        }
        g_Y[(size_t)c*P_ + pbase + k] = val;
    }
}

// ---------------- weight transpose: W[M][K] -> Wt[K][M] ----------------------
__global__ void transposeW(const float* __restrict__ W, float* __restrict__ Wt,
                           int M, int Kk)
{
    int i = blockIdx.x * 256 + threadIdx.x;
    if (i < M * Kk){
        int m = i / Kk, k = i - m * Kk;
        Wt[(long)k * M + m] = W[i];
    }
}

// ------------- double-buffered conv GEMM: 128x128 tile, 8x8/thread ----------
__global__ void __launch_bounds__(256, 2)
gemm128db(const float* __restrict__ At, const float* __restrict__ Bm,
          float* __restrict__ C, int M, int Nn, int Kk)
{
    __shared__ float As[2][8][128];
    __shared__ float Bs[2][8][128];
    int tid = threadIdx.x;
    int n0 = blockIdx.x * 128, m0 = blockIdx.y * 128;
    int lr = tid >> 5;              // 0..7 (k within tile)
    int lc = (tid & 31) << 2;       // 0..124
    int tx = tid & 15, ty = tid >> 4;

    const float4 z4 = make_float4(0.f,0.f,0.f,0.f);
    {
        float4 av = (lr < Kk) ? *(const float4*)(At + (long)lr*M  + m0 + lc) : z4;
        float4 bv = (lr < Kk) ? *(const float4*)(Bm + (long)lr*Nn + n0 + lc) : z4;
        *(float4*)&As[0][lr][lc] = av;
        *(float4*)&Bs[0][lr][lc] = bv;
    }
    __syncthreads();

    float acc[8][8] = {};
    int buf = 0;
    for (int k0 = 8; k0 < Kk; k0 += 8){
        int kg = k0 + lr;
        float4 av = (kg < Kk) ? *(const float4*)(At + (long)kg*M  + m0 + lc) : z4;
        float4 bv = (kg < Kk) ? *(const float4*)(Bm + (long)kg*Nn + n0 + lc) : z4;
#pragma unroll
        for (int kk = 0; kk < 8; kk++){
            float4 a0 = *(const float4*)&As[buf][kk][ty*4];
            float4 a1 = *(const float4*)&As[buf][kk][ty*4 + 64];
            float4 b0 = *(const float4*)&Bs[buf][kk][tx*4];
            float4 b1 = *(const float4*)&Bs[buf][kk][tx*4 + 64];
            float a_[8] = {a0.x,a0.y,a0.z,a0.w,a1.x,a1.y,a1.z,a1.w};
            float b_[8] = {b0.x,b0.y,b0.z,b0.w,b1.x,b1.y,b1.z,b1.w};
#pragma unroll
            for (int i = 0; i < 8; i++)
#pragma unroll
                for (int j = 0; j < 8; j++)
                    acc[i][j] = fmaf(a_[i], b_[j], acc[i][j]);
        }
        *(float4*)&As[buf^1][lr][lc] = av;
        *(float4*)&Bs[buf^1][lr][lc] = bv;
        __syncthreads();
        buf ^= 1;
    }
#pragma unroll
    for (int kk = 0; kk < 8; kk++){
        float4 a0 = *(const float4*)&As[buf][kk][ty*4];
        float4 a1 = *(const float4*)&As[buf][kk][ty*4 + 64];
        float4 b0 = *(const float4*)&Bs[buf][kk][tx*4];
        float4 b1 = *(const float4*)&Bs[buf][kk][tx*4 + 64];
        float a_[8] = {a0.x,a0.y,a0.z,a0.w,a1.x,a1.y,a1.z,a1.w};
        float b_[8] = {b0.x,b0.y,b0.z,b0.w,b1.x,b1.y,b1.z,b1.w};
#pragma unroll
        for (int i = 0; i < 8; i++)
#pragma unroll
            for (int j = 0; j < 8; j++)
                acc[i][j] = fmaf(a_[i], b_[j], acc[i][j]);
    }

#pragma unroll
    for (int i = 0; i < 8; i++){
        int mm = m0 + ((i < 4) ? ty*4 + i : 64 + ty*4 + (i-4));
        float* crow = C + (long)mm*Nn + n0;
        *(float4*)&crow[tx*4]      = make_float4(acc[i][0],acc[i][1],acc[i][2],acc[i][3]);
        *(float4*)&crow[tx*4 + 64] = make_float4(acc[i][4],acc[i][5],acc[i][6],acc[i][7]);
    }
}

// ---------------- small GEMMs (64x64 tile) for attention --------------------
__global__ void gemm_nn(const float* __restrict__ A, const float* __restrict__ Bm,
                        float* __restrict__ C, const float* __restrict__ bias,
                        int M, int Nn, int Kk, long sA, long sB, long sC)
{
    A  += (long)blockIdx.z * sA;
    Bm += (long)blockIdx.z * sB;
    C  += (long)blockIdx.z * sC;
    __shared__ float As[16][68];
    __shared__ float Bs[16][64];
    int tid = threadIdx.x;
    int m0 = blockIdx.y * 64, n0 = blockIdx.x * 64;
    int ty = tid >> 4, tx = tid & 15;
    float acc[4][4] = {};
    for (int k0 = 0; k0 < Kk; k0 += 16){
#pragma unroll
        for (int i = tid; i < 1024; i += 256){
            int rr = i >> 4, cc = i & 15;
            int mm = m0 + rr, kk = k0 + cc;
            As[cc][rr] = (mm < M && kk < Kk) ? A[(long)mm*Kk + kk] : 0.f;
        }
#pragma unroll
        for (int i = tid; i < 1024; i += 256){
            int rr = i >> 6, cc = i & 63;
            int kk = k0 + rr;
            Bs[rr][cc] = (kk < Kk) ? Bm[(long)kk*Nn + n0 + cc] : 0.f;
        }
        __syncthreads();
#pragma unroll
        for (int kk = 0; kk < 16; kk++){
            float4 a  = *(const float4*)&As[kk][ty*4];
            float4 bv = *(const float4*)&Bs[kk][tx*4];
            float av[4] = {a.x, a.y, a.z, a.w};
            float bb[4] = {bv.x, bv.y, bv.z, bv.w};
#pragma unroll
            for (int i = 0; i < 4; i++)
#pragma unroll
                for (int j = 0; j < 4; j++)
                    acc[i][j] = fmaf(av[i], bb[j], acc[i][j]);
        }
        __syncthreads();
    }
#pragma unroll
    for (int i = 0; i < 4; i++){
        int mm = m0 + ty*4 + i;
        if (mm < M){
            float bsv = bias ? bias[mm] : 0.f;
            float4 o = make_float4(acc[i][0]+bsv, acc[i][1]+bsv, acc[i][2]+bsv, acc[i][3]+bsv);
            *(float4*)&C[(long)mm*Nn + n0 + tx*4] = o;
        }
    }
}

__global__ void gemm_tn(const float* __restrict__ A, const float* __restrict__ Bm,
                        float* __restrict__ C,
                        int M, int Nn, int Kk, int lda, int ldb,
                        long sA, long sB, long sC)
{
    A += (long)blockIdx.z*sA; Bm += (long)blockIdx.z*sB; C += (long)blockIdx.z*sC;
    __shared__ float As[16][64], Bs[16][64];
    int tid = threadIdx.x;
    int m0 = blockIdx.y * 64, n0 = blockIdx.x * 64;
    int ty = tid >> 4, tx = tid & 15;
    float acc[4][4] = {};
    for (int k0 = 0; k0 < Kk; k0 += 16){
#pragma unroll
        for (int i = tid; i < 1024; i += 256){
            int rr = i >> 6, cc = i & 63;
            int kk = k0 + rr;
            As[rr][cc] = (kk < Kk) ? A[(long)kk*lda + m0 + cc] : 0.f;
            Bs[rr][cc] = (kk < Kk) ? Bm[(long)kk*ldb + n0 + cc] : 0.f;
        }
        __syncthreads();
#pragma unroll
        for (int kk = 0; kk < 16; kk++){
            float4 a  = *(const float4*)&As[kk][ty*4];
            float4 bv = *(const float4*)&Bs[kk][tx*4];
            float av[4] = {a.x, a.y, a.z, a.w};
            float bb[4] = {bv.x, bv.y, bv.z, bv.w};
#pragma unroll
            for (int i = 0; i < 4; i++)
#pragma unroll
                for (int j = 0; j < 4; j++)
                    acc[i][j] = fmaf(av[i], bb[j], acc[i][j]);
        }
        __syncthreads();
    }
#pragma unroll
    for (int i = 0; i < 4; i++){
        int mm = m0 + ty*4 + i;
        float4 o = make_float4(acc[i][0], acc[i][1], acc[i][2], acc[i][3]);
        *(float4*)&C[(long)mm*Nn + n0 + tx*4] = o;
    }
}

__global__ void gemm_nt(const float* __restrict__ A, const float* __restrict__ Bm,
                        float* __restrict__ C,
                        int M, int Nn, int Kk, int lda, int ldb,
                        long sA, long sB, long sC)
{
    A += (long)blockIdx.z*sA; Bm += (long)blockIdx.z*sB; C += (long)blockIdx.z*sC;
    __shared__ float As[16][68], Bs[16][68];
    int tid = threadIdx.x;
    int m0 = blockIdx.y * 64, n0 = blockIdx.x * 64;
    int ty = tid >> 4, tx = tid & 15;
    float acc[4][4] = {};
    for (int k0 = 0; k0 < Kk; k0 += 16){
#pragma unroll
        for (int i = tid; i < 1024; i += 256){
            int mm = i >> 4, kd = i & 15;
            int kk = k0 + kd;
            As[kd][mm] = (kk < Kk) ? A[(long)(m0+mm)*lda + kk] : 0.f;
            Bs[kd][mm] = (kk < Kk) ? Bm[(long)(n0+mm)*ldb + kk] : 0.f;
        }
        __syncthreads();
#pragma unroll
        for (int kk = 0; kk < 16; kk++){
            float4 a  = *(const float4*)&As[kk][ty*4];
            float4 bv = *(const float4*)&Bs[kk][tx*4];
            float av[4] = {a.x, a.y, a.z, a.w};
            float bb[4] = {bv.x, bv.y, bv.z, bv.w};
#pragma unroll
            for (int i = 0; i < 4; i++)
#pragma unroll
                for (int j = 0; j < 4; j++)
                    acc[i][j] = fmaf(av[i], bb[j], acc[i][j]);
        }
        __syncthreads();
    }
#pragma unroll
    for (int i = 0; i < 4; i++){
        int mm = m0 + ty*4 + i;
        float4 o = make_float4(acc[i][0], acc[i][1], acc[i][2], acc[i][3]);
        *(float4*)&C[(long)mm*Nn + n0 + tx*4] = o;
    }
}

// ---- Kahan-compensated fp32 GEMMs for the channel-attention path ----------
// NT: C[m][n] = sum_k A[m*lda+k] * B[n*ldb+k], compensated accumulation
__global__ void gemm_nt_kah(const float* __restrict__ A, const float* __restrict__ Bm,
                            float* __restrict__ C,
                            int M, int Nn, int Kk, int lda, int ldb,
                            long sA, long sB, long sC)
{
    A += (long)blockIdx.z*sA; Bm += (long)blockIdx.z*sB; C += (long)blockIdx.z*sC;
    __shared__ float As[16][68], Bs[16][68];
    int tid = threadIdx.x;
    int m0 = blockIdx.y * 64, n0 = blockIdx.x * 64;
    int ty = tid >> 4, tx = tid & 15;
    float acc[4][4] = {};
    float cmp[4][4] = {};
    for (int k0 = 0; k0 < Kk; k0 += 16){
#pragma unroll
        for (int i = tid; i < 1024; i += 256){
            int mm = i >> 4, kd = i & 15;
            int kk = k0 + kd;
            As[kd][mm] = (kk < Kk) ? A[(long)(m0+mm)*lda + kk] : 0.f;
            Bs[kd][mm] = (kk < Kk) ? Bm[(long)(n0+mm)*ldb + kk] : 0.f;
        }
        __syncthreads();
#pragma unroll
        for (int kk = 0; kk < 16; kk++){
            float4 a  = *(const float4*)&As[kk][ty*4];
            float4 bv = *(const float4*)&Bs[kk][tx*4];
            float av[4] = {a.x, a.y, a.z, a.w};
            float bb[4] = {bv.x, bv.y, bv.z, bv.w};
#pragma unroll
            for (int i = 0; i < 4; i++)
#pragma unroll
                for (int j = 0; j < 4; j++){
                    float y = fmaf(av[i], bb[j], -cmp[i][j]);
                    float t = acc[i][j] + y;
                    cmp[i][j] = (t - acc[i][j]) - y;
                    acc[i][j] = t;
                }
        }
        __syncthreads();
    }
#pragma unroll
    for (int i = 0; i < 4; i++){
        int mm = m0 + ty*4 + i;
        float4 o = make_float4(acc[i][0], acc[i][1], acc[i][2], acc[i][3]);
        *(float4*)&C[(long)mm*Nn + n0 + tx*4] = o;
    }
}

// NN: C[m][n] = sum_k A[m*Kk+k] * B[k*Nn+n], compensated accumulation
__global__ void gemm_nn_kah(const float* __restrict__ A, const float* __restrict__ Bm,
                            float* __restrict__ C,
                            int M, int Nn, int Kk, long sA, long sB, long sC)
{
    A  += (long)blockIdx.z * sA;
    Bm += (long)blockIdx.z * sB;
    C  += (long)blockIdx.z * sC;
    __shared__ float As[16][68];
    __shared__ float Bs[16][64];
    int tid = threadIdx.x;
    int m0 = blockIdx.y * 64, n0 = blockIdx.x * 64;
    int ty = tid >> 4, tx = tid & 15;
    float acc[4][4] = {};
    float cmp[4][4] = {};
    for (int k0 = 0; k0 < Kk; k0 += 16){
#pragma unroll
        for (int i = tid; i < 1024; i += 256){
            int rr = i >> 4, cc = i & 15;
            int mm = m0 + rr, kk = k0 + cc;
            As[cc][rr] = (mm < M && kk < Kk) ? A[(long)mm*Kk + kk] : 0.f;
        }
#pragma unroll
        for (int i = tid; i < 1024; i += 256){
            int rr = i >> 6, cc = i & 63;
            int kk = k0 + rr;
            Bs[rr][cc] = (kk < Kk) ? Bm[(long)kk*Nn + n0 + cc] : 0.f;
        }
        __syncthreads();
#pragma unroll
        for (int kk = 0; kk < 16; kk++){
            float4 a  = *(const float4*)&As[kk][ty*4];
            float4 bv = *(const float4*)&Bs[kk][tx*4];
            float av[4] = {a.x, a.y, a.z, a.w};
            float bb[4] = {bv.x, bv.y, bv.z, bv.w};
#pragma unroll
            for (int i = 0; i < 4; i++)
#pragma unroll
                for (int j = 0; j < 4; j++){
                    float y = fmaf(av[i], bb[j], -cmp[i][j]);
                    float t = acc[i][j] + y;
                    cmp[i][j] = (t - acc[i][j]) - y;
                    acc[i][j] = t;
                }
        }
        __syncthreads();
    }
#pragma unroll
    for (int i = 0; i < 4; i++){
        int mm = m0 + ty*4 + i;
        float4 o = make_float4(acc[i][0], acc[i][1], acc[i][2], acc[i][3]);
        *(float4*)&C[(long)mm*Nn + n0 + tx*4] = o;
    }
}

// ---------------- BatchNorm (training mode) ---------------------------------
__global__ void bn_stats_part(const float* __restrict__ Xs)
{
    int c = blockIdx.x, blk = blockIdx.y;
    const float4* xp = (const float4*)(Xs + (size_t)c * P_ + (size_t)blk * (P_/8));
    int tid = threadIdx.x;
    double s = 0.0, ss = 0.0;
    const int nvec = (P_/8)/4;
    for (int p = tid; p < nvec; p += 256){
        float4 v = xp[p];
        s  += (double)v.x + (double)v.y + (double)v.z + (double)v.w;
        ss += (double)v.x*v.x + (double)v.y*v.y + (double)v.z*v.z + (double)v.w*v.w;
    }
    __shared__ double sh0[256], sh1[256];
    sh0[tid] = s; sh1[tid] = ss; __syncthreads();
    for (int off = 128; off; off >>= 1){
        if (tid < off){ sh0[tid] += sh0[tid+off]; sh1[tid] += sh1[tid+off]; }
        __syncthreads();
    }
    if (tid == 0){
        g_part[(c*8 + blk)*2 + 0] = sh0[0];
        g_part[(c*8 + blk)*2 + 1] = sh1[0];
    }
}

__global__ void bn_stats_final(int C)
{
    int c = threadIdx.x;
    if (c < C){
        double s = 0.0, ss = 0.0;
#pragma unroll
        for (int j = 0; j < 8; j++){
            s  += g_part[(c*8+j)*2+0];
            ss += g_part[(c*8+j)*2+1];
        }
        double m   = s / (double)P_;
        double var = ss / (double)P_ - m*m;
        g_mean[c] = (float)m;
        g_istd[c] = (float)(1.0 / sqrt(var + 1e-5));
    }
}

__global__ void bn_apply_relu(const float* __restrict__ Xs, float* __restrict__ dst,
                              const float* __restrict__ gg, const float* __restrict__ be)
{
    size_t i = (size_t)blockIdx.x * 256 + threadIdx.x;    // float4 index
    int c = (int)(i >> 15);
    float m = g_mean[c], is = g_istd[c], gv = gg[c], bb = be[c];
    float4 v = ((const float4*)Xs)[i];
    float4 o;
    o.x = fmaxf((v.x - m)*is*gv + bb, 0.f);
    o.y = fmaxf((v.y - m)*is*gv + bb, 0.f);
    o.z = fmaxf((v.z - m)*is*gv + bb, 0.f);
    o.w = fmaxf((v.w - m)*is*gv + bb, 0.f);
    ((float4*)dst)[i] = o;
}

// ------- fused layer-4 BN + ReLU + max over K --------------------------------
__global__ void bn_relu_maxk(const float* __restrict__ Xs,
                             const float* __restrict__ gg, const float* __restrict__ be)
{
    int i = blockIdx.x * 256 + threadIdx.x;           // over B*COUT*S = 2^20
    int s = i & 1023, c = (i >> 10) & 255, b = i >> 18;
    float m = g_mean[c], is = g_istd[c], gv = gg[c], bb = be[c];
    float sc = is * gv;
    const float4* src = (const float4*)(Xs + (size_t)c * P_ + ((size_t)(b*S_ + s)) * K_);
    float best = 0.f;
#pragma unroll
    for (int k = 0; k < 8; k++){
        float4 v = src[k];
        best = fmaxf(best, (v.x - m)*sc + bb);
        best = fmaxf(best, (v.y - m)*sc + bb);
        best = fmaxf(best, (v.z - m)*sc + bb);
        best = fmaxf(best, (v.w - m)*sc + bb);
    }
    g_feat[i] = best;
}

// ---------------- softmaxes ---------------------------------------------------
__global__ void softmax_rows_1024(float* __restrict__ E)
{
    int row = blockIdx.x;
    float* e = E + (size_t)row * 1024;
    int tid = threadIdx.x;
    __shared__ float sh[256];
    float mx = -3.402823466e38f;
    for (int c = tid; c < 1024; c += 256) mx = fmaxf(mx, e[c]);
    sh[tid] = mx; __syncthreads();
    for (int off = 128; off; off >>= 1){ if (tid < off) sh[tid] = fmaxf(sh[tid], sh[tid+off]); __syncthreads(); }
    mx = sh[0]; __syncthreads();
    float sum = 0.f;
    float vals[4];
#pragma unroll
    for (int q = 0; q < 4; q++){
        int c = tid + q*256;
        float v = expf(e[c] - mx);
        vals[q] = v; sum += v;
    }
    sh[tid] = sum; __syncthreads();
    for (int off = 128; off; off >>= 1){ if (tid < off) sh[tid] += sh[tid+off]; __syncthreads(); }
    float inv = 1.0f / sh[0];
#pragma unroll
    for (int q = 0; q < 4; q++) e[tid + q*256] = vals[q] * inv;
}

__global__ void softmax_c_kernel(float* __restrict__ E)
{
    int row = blockIdx.x;                   // B*COUT rows of 256
    float* e = E + (size_t)row * 256;
    int tid = threadIdx.x;
    __shared__ double sh[256];
    double v = (double)e[tid];
    sh[tid] = v; __syncthreads();
    for (int off = 128; off; off >>= 1){ if (tid < off) sh[tid] = fmax(sh[tid], sh[tid+off]); __syncthreads(); }
    double m1 = sh[0]; __syncthreads();
    double t = m1 - v;
    sh[tid] = t; __syncthreads();
    for (int off = 128; off; off >>= 1){ if (tid < off) sh[tid] = fmax(sh[tid], sh[tid+off]); __syncthreads(); }
    double mt = sh[0]; __syncthreads();
    double ex = exp(t - mt);
    sh[tid] = ex; __syncthreads();
    for (int off = 128; off; off >>= 1){ if (tid < off) sh[tid] += sh[tid+off]; __syncthreads(); }
    e[tid] = (float)(ex / sh[0]);
}

// ---------------- finalize -----------------------------------------------------
__global__ void finalize_kernel(float* __restrict__ out, const float* __restrict__ gamma)
{
    int i = blockIdx.x * 256 + threadIdx.x;   // output-major (b,s,c), 2^20 total
    int c = i & 255, s = (i >> 8) & 1023, b = i >> 18;
    size_t f = ((size_t)(b*COUT_ + c)) * S_ + s;
    float g = gamma[0];
    float val = g * (g_outp[f] + g_outc[f]) + 2.0f * g_feat[f];
    out[(size_t)B_*S_*3 + i] = val;
}

// ---------------- launch -------------------------------------------------------
extern "C" void kernel_launch(void* const* d_in, const int* in_sizes, int n_in,
                              void* d_out, int out_size)
{
    const float* xyz    = (const float*)d_in[0];
    const float* points = (const float*)d_in[1];
    const float* W[4]  = {(const float*)d_in[2],  (const float*)d_in[6],
                          (const float*)d_in[10], (const float*)d_in[14]};
    const float* gl[4] = {(const float*)d_in[4],  (const float*)d_in[8],
                          (const float*)d_in[12], (const float*)d_in[16]};
    const float* bel[4]= {(const float*)d_in[5],  (const float*)d_in[9],
                          (const float*)d_in[13], (const float*)d_in[17]};
    const float* Wq = (const float*)d_in[18]; const float* bq = (const float*)d_in[19];
    const float* Wk = (const float*)d_in[20]; const float* bk = (const float*)d_in[21];
    const float* Wv = (const float*)d_in[22]; const float* bv = (const float*)d_in[23];
    const float* gamma = (const float*)d_in[24];
    float* out = (float*)d_out;

    float *Y, *Xs, *Wt, *feat, *q, *k, *v, *E, *Ec, *outp, *outc;
    cudaGetSymbolAddress((void**)&Y,    g_Y);
    cudaGetSymbolAddress((void**)&Xs,   g_Xs);
    cudaGetSymbolAddress((void**)&Wt,   g_Wt);
    cudaGetSymbolAddress((void**)&feat, g_feat);
    cudaGetSymbolAddress((void**)&q,    g_q);
    cudaGetSymbolAddress((void**)&k,    g_k);
    cudaGetSymbolAddress((void**)&v,    g_v);
    cudaGetSymbolAddress((void**)&E,    g_E);
    cudaGetSymbolAddress((void**)&Ec,   g_Ec);
    cudaGetSymbolAddress((void**)&outp, g_outp);
    cudaGetSymbolAddress((void**)&outc, g_outc);

    // stage 1-2: FPS, ball query, gather/build x0
    fps_kernel<<<B_, 1024>>>(xyz, out);
    ball_kernel<<<(B_*S_*32)/256, 256>>>(xyz);
    build_x0<<<B_*S_, 256>>>(xyz, points);

    // stage 3: DenseNet (transpose W -> conv -> BN stats -> BN+relu)
    int   Kl[4]  = {CIN_, CIN_+HID_, CIN_+2*HID_, CIN_+3*HID_};
    int   COl[4] = {HID_, HID_, HID_, COUT_};
    float* dst[4] = {Y + (size_t)CIN_*P_, Y + (size_t)(CIN_+HID_)*P_,
                     Y + (size_t)(CIN_+2*HID_)*P_, nullptr};
    for (int l = 0; l < 4; l++){
        int Melem = COl[l]*Kl[l];
        transposeW<<<(Melem + 255)/256, 256>>>(W[l], Wt, COl[l], Kl[l]);
        gemm128db<<<dim3(P_/128, COl[l]/128), 256>>>(Wt, Y, Xs, COl[l], P_, Kl[l]);
        bn_stats_part<<<dim3(COl[l], 8), 256>>>(Xs);
        bn_stats_final<<<1, 256>>>(COl[l]);
        if (l < 3)
            bn_apply_relu<<<(COl[l]*(P_/1024)), 256>>>(Xs, dst[l], gl[l], bel[l]);
        else
            bn_relu_maxk<<<(B_*COUT_*S_)/256, 256>>>(Xs, gl[l], bel[l]);
    }

    // stage 5: dual attention
    long fS = (long)COUT_ * S_;
    gemm_nn<<<dim3(S_/64, 1, B_), 256>>>(Wq, feat, q, bq, C8_,  S_, COUT_, 0, fS, (long)C8_*S_);
    gemm_nn<<<dim3(S_/64, 1, B_), 256>>>(Wk, feat, k, bk, C8_,  S_, COUT_, 0, fS, (long)C8_*S_);
    gemm_nn<<<dim3(S_/64, 4, B_), 256>>>(Wv, feat, v, bv, COUT_,S_, COUT_, 0, fS, fS);

    gemm_tn<<<dim3(S_/64, S_/64, B_), 256>>>(q, k, E, S_, S_, C8_, S_, S_,
                                             (long)C8_*S_, (long)C8_*S_, (long)S_*S_);
    softmax_rows_1024<<<B_*S_, 256>>>(E);
    gemm_nt<<<dim3(S_/64, COUT_/64, B_), 256>>>(v, E, outp, COUT_, S_, S_, S_, S_,
                                                fS, (long)S_*S_, fS);

    // channel attention — Kahan-compensated fp32 energy + out_c, f64 softmax
    gemm_nt_kah<<<dim3(COUT_/64, COUT_/64, B_), 256>>>(
        feat, feat, Ec, COUT_, COUT_, S_, S_, S_, fS, fS, (long)COUT_*COUT_);
    softmax_c_kernel<<<B_*COUT_, 256>>>(Ec);
    gemm_nn_kah<<<dim3(S_/64, COUT_/64, B_), 256>>>(
        Ec, feat, outc, COUT_, S_, COUT_, (long)COUT_*COUT_, fS, fS);

    finalize_kernel<<<(B_*S_*COUT_)/256, 256>>>(out, gamma);
}